// round 11
// baseline (speedup 1.0000x reference)
#include <cuda_runtime.h>
#include <math.h>
#include <stdint.h>

#define TOK 4096          // B*T
#define CH  1024          // C
#define NH  16            // heads
#define HS  64            // head size
#define NUP 384           // packed LoRA hidden width
#define STAGES 3
#define ROWW 24           // smem row stride in words (16 data + 8 pad; conflict-free LDS.64)
#define MATW (STAGES * 128 * ROWW)          // words per matrix buffer
#define SMEM_BYTES (2 * MATW * 4)           // 73728 B dynamic smem (GEMM)
#define REC_SMEM (2 * 7 * 16 * 64 * 4)      // 57344 B dynamic smem (rec)

static constexpr size_t SZ = (size_t)TOK * CH;

static constexpr size_t OFF_XR   = 0 * SZ;
static constexpr size_t OFF_XW   = 1 * SZ;
static constexpr size_t OFF_XK   = 2 * SZ;
static constexpr size_t OFF_XV   = 3 * SZ;
static constexpr size_t OFF_XA   = 4 * SZ;
static constexpr size_t OFF_XG   = 5 * SZ;
static constexpr size_t OFF_R    = 6 * SZ;   // R,K,V contiguous (raw projections)
static constexpr size_t OFF_K    = 7 * SZ;
static constexpr size_t OFF_V    = 8 * SZ;
static constexpr size_t OFF_TW   = 9 * SZ;   // TW,TA,TV,GATE contiguous (dn outputs)
static constexpr size_t OFF_TA   = 10 * SZ;
static constexpr size_t OFF_TV   = 11 * SZ;
static constexpr size_t OFF_GATE = 12 * SZ;
static constexpr size_t OFF_KN   = 13 * SZ;  // rec-computed kn (for post bonus)
static constexpr size_t OFF_NV   = 14 * SZ;  // rec-computed nv (for post bonus)
static constexpr size_t OFF_Y    = 16 * SZ;
static constexpr size_t OFF_YP   = 17 * SZ;
static constexpr size_t OFF_H    = 18 * SZ;                          // [TOK][384] (k-permuted cols)
static constexpr size_t OFF_H1   = 18 * SZ + (size_t)TOK * NUP;      // split-K partial
static constexpr size_t OFF_WUPT = 19 * SZ;                          // [640][1024] n-major (tf32, k-perm)
static constexpr size_t OFF_WDNT = 19 * SZ + (size_t)640 * 1024;     // [1024][384] n-major (tf32, k-perm)
static constexpr size_t OFF_WB   = 20 * SZ;                          // Wr|Wk|Wv|Wo tf32 (k-perm), 1M each
static constexpr size_t TOTALF   = 21 * SZ;

__device__ float g_buf[TOTALF];

__device__ __forceinline__ float rtf32(float f) {
    uint32_t u; asm("cvt.rna.tf32.f32 %0, %1;" : "=r"(u) : "f"(f));
    return __uint_as_float(u);
}

// k-permutation within each 8-group: P(k) = (k&~7) | ((k&3)<<1) | ((k>>2)&1)
__device__ __forceinline__ int pcol(int k) {
    return (k & ~7) | ((k & 3) << 1) | ((k >> 2) & 1);
}

__device__ __forceinline__ void cp16(uint32_t dst, const float* src) {
    asm volatile("cp.async.cg.shared.global [%0], [%1], 16;" :: "r"(dst), "l"(src));
}

// ---------------------------------------------------------------------------
// 1) token-shift mixes (tf32-rounded, k-permuted: feed GEMMs only)
// ---------------------------------------------------------------------------
__global__ void __launch_bounds__(256) mix_kernel(
    const float* __restrict__ x,
    const float* __restrict__ mr, const float* __restrict__ mw,
    const float* __restrict__ mk, const float* __restrict__ mv,
    const float* __restrict__ ma, const float* __restrict__ mg)
{
    int idx = blockIdx.x * 256 + threadIdx.x;
    int c   = idx & (CH - 1);
    int row = idx >> 10;
    int t   = row & 1023;
    float xv = x[idx];
    float lx = (t == 0) ? 0.f : x[idx - CH];
    float dx = lx - xv;
    size_t w = (size_t)row * CH + pcol(c);
    g_buf[OFF_XR + w] = rtf32(fmaf(mr[c], dx, xv));
    g_buf[OFF_XW + w] = rtf32(fmaf(mw[c], dx, xv));
    g_buf[OFF_XK + w] = rtf32(fmaf(mk[c], dx, xv));
    g_buf[OFF_XV + w] = rtf32(fmaf(mv[c], dx, xv));
    g_buf[OFF_XA + w] = rtf32(fmaf(ma[c], dx, xv));
    g_buf[OFF_XG + w] = rtf32(fmaf(mg[c], dx, xv));
}

// ---------------------------------------------------------------------------
// weight packs (tf32-rounded, k-permuted)
// ---------------------------------------------------------------------------
__global__ void __launch_bounds__(256) pack_up_kernel(
    const float* __restrict__ w1, const float* __restrict__ a1,
    const float* __restrict__ v1, const float* __restrict__ g1)
{
    int idx = blockIdx.x * 256 + threadIdx.x;   // < 640*1024
    if (idx >= 640 * 1024) return;
    int n = idx >> 10;
    int k = idx & 1023;
    float v = 0.f;
    if      (n < 64)                 v = w1[k * 64  + n];
    else if (n >= 128 && n < 192)    v = a1[k * 64  + (n - 128)];
    else if (n >= 256 && n < 288)    v = v1[k * 32  + (n - 256)];
    else if (n >= 384 && n < 544)    v = g1[k * 160 + (n - 384)];
    g_buf[OFF_WUPT + ((size_t)n << 10) + pcol(k)] = rtf32(v);
}

__global__ void __launch_bounds__(256) pack_dn_kernel(
    const float* __restrict__ w2, const float* __restrict__ a2,
    const float* __restrict__ v2, const float* __restrict__ g2)
{
    int idx = blockIdx.x * 256 + threadIdx.x;       // < 1024*384
    if (idx >= 1024 * NUP) return;
    int n  = idx / NUP;
    int kk = idx - n * NUP;
    float v;
    if      (kk < 64)  v = w2[(size_t)kk * 1024 + n];
    else if (kk < 128) v = a2[(size_t)(kk - 64) * 1024 + n];
    else if (kk < 160) v = v2[(size_t)(kk - 128) * 1024 + n];
    else if (kk < 192) v = 0.f;
    else if (kk < 352) v = g2[(size_t)(kk - 192) * 1024 + n];
    else               v = 0.f;
    g_buf[OFF_WDNT + (size_t)n * NUP + pcol(kk)] = rtf32(v);
}

__global__ void __launch_bounds__(256) pack_rkvo_kernel(
    const float* __restrict__ Wr, const float* __restrict__ Wk,
    const float* __restrict__ Wv, const float* __restrict__ Wo)
{
    int idx = blockIdx.x * 256 + threadIdx.x;   // < 4*1M
    int m = idx >> 20;
    int e = idx & ((1 << 20) - 1);
    int n = e >> 10;
    int k = e & 1023;
    const float* src = (m == 0) ? Wr : (m == 1) ? Wk : (m == 2) ? Wv : Wo;
    g_buf[OFF_WB + ((size_t)m << 20) + ((size_t)n << 10) + pcol(k)] = rtf32(src[e]);
}

// ---------------------------------------------------------------------------
// tf32 MMA core, cp.async 3-stage pipeline (NT), k-permuted inputs (R9 config).
// ---------------------------------------------------------------------------
__device__ __forceinline__ void gemm_async_core(
    float* sm, const float* A, int lda, const float* B, int ldb,
    float* C, int ldc, int K, int m0, int n0, int col_off, int width, int permout)
{
    const int tid  = threadIdx.x;
    const int lane = tid & 31, warp = tid >> 5;
    const int wm = warp >> 2, wn = warp & 3;

    float* smA = sm;
    float* smB = sm + MATW;
    const uint32_t saA = (uint32_t)__cvta_generic_to_shared(smA);
    const uint32_t saB = (uint32_t)__cvta_generic_to_shared(smB);

    const int rowc = tid >> 1;
    const int jj4  = (tid & 1) * 8;
    const float* Abase = A + (size_t)(m0 + rowc) * lda + jj4;
    const float* Bbase = B + (size_t)(n0 + rowc) * ldb + jj4;
    const uint32_t soff = (uint32_t)((rowc * ROWW + jj4) * 4);

    float acc[4][4][4];
#pragma unroll
    for (int mt = 0; mt < 4; mt++)
#pragma unroll
        for (int nt = 0; nt < 4; nt++)
#pragma unroll
            for (int r = 0; r < 4; r++) acc[mt][nt][r] = 0.f;

    auto issue = [&](int s, int k0) {
        uint32_t da = saA + (uint32_t)(s * 128 * ROWW * 4) + soff;
        uint32_t db = saB + (uint32_t)(s * 128 * ROWW * 4) + soff;
        cp16(da,      Abase + k0);
        cp16(da + 16, Abase + k0 + 4);
        cp16(db,      Bbase + k0);
        cp16(db + 16, Bbase + k0 + 4);
    };

#pragma unroll
    for (int s = 0; s < STAGES - 1; s++) {
        if (s * 16 < K) issue(s, s * 16);
        asm volatile("cp.async.commit_group;" ::: "memory");
    }

    const int q2 = (lane & 3) * 2;

    int stage = 0;
    for (int k0 = 0; k0 < K; k0 += 16) {
        asm volatile("cp.async.wait_group 1;" ::: "memory");
        __syncthreads();
        int kn = k0 + (STAGES - 1) * 16;
        if (kn < K) {
            int sn = stage + (STAGES - 1); if (sn >= STAGES) sn -= STAGES;
            issue(sn, kn);
        }
        asm volatile("cp.async.commit_group;" ::: "memory");

        const float* As = smA + stage * 128 * ROWW;
        const float* Bs = smB + stage * 128 * ROWW;
#pragma unroll
        for (int kk = 0; kk < 2; kk++) {
            const int base = kk * 8 + q2;
            uint2 ap0[4], ap1[4], bp[4];
#pragma unroll
            for (int mt = 0; mt < 4; mt++) {
                int r = wm * 64 + mt * 16 + (lane >> 2);
                ap0[mt] = *(const uint2*)&As[r * ROWW + base];        // (c, c+4)
                ap1[mt] = *(const uint2*)&As[(r + 8) * ROWW + base];
            }
#pragma unroll
            for (int nt = 0; nt < 4; nt++) {
                int n = wn * 32 + nt * 8 + (lane >> 2);
                bp[nt] = *(const uint2*)&Bs[n * ROWW + base];
            }
#pragma unroll
            for (int mt = 0; mt < 4; mt++)
#pragma unroll
                for (int nt = 0; nt < 4; nt++) {
                    asm volatile(
                        "mma.sync.aligned.m16n8k8.row.col.f32.tf32.tf32.f32 "
                        "{%0,%1,%2,%3},{%4,%5,%6,%7},{%8,%9},{%0,%1,%2,%3};"
                        : "+f"(acc[mt][nt][0]), "+f"(acc[mt][nt][1]),
                          "+f"(acc[mt][nt][2]), "+f"(acc[mt][nt][3])
                        : "r"(ap0[mt].x), "r"(ap1[mt].x),
                          "r"(ap0[mt].y), "r"(ap1[mt].y),
                          "r"(bp[nt].x), "r"(bp[nt].y));
                }
        }
        stage = (stage + 1 == STAGES) ? 0 : stage + 1;
    }

#pragma unroll
    for (int mt = 0; mt < 4; mt++) {
        int row = m0 + wm * 64 + mt * 16 + (lane >> 2);
#pragma unroll
        for (int nt = 0; nt < 4; nt++) {
            int col = wn * 32 + nt * 8 + (lane & 3) * 2;
            if (col < width) {
                if (permout) {
                    int p0 = pcol(n0 + col), p1 = pcol(n0 + col + 1);
                    C[(size_t)row * ldc + col_off + p0] = acc[mt][nt][0];
                    C[(size_t)row * ldc + col_off + p1] = acc[mt][nt][1];
                    C[(size_t)(row + 8) * ldc + col_off + p0] = acc[mt][nt][2];
                    C[(size_t)(row + 8) * ldc + col_off + p1] = acc[mt][nt][3];
                } else {
                    int gcol = n0 + col;
                    *(float2*)(C + (size_t)row * ldc + col_off + gcol) =
                        make_float2(acc[mt][nt][0], acc[mt][nt][1]);
                    *(float2*)(C + (size_t)(row + 8) * ldc + col_off + gcol) =
                        make_float2(acc[mt][nt][2], acc[mt][nt][3]);
                }
            }
        }
    }
}

__global__ void __launch_bounds__(256) gemm_nt_async(
    const float* __restrict__ A, int lda,
    const float* __restrict__ B, int ldb,
    float* __restrict__ C, int ldc, int K)
{
    extern __shared__ float sm[];
    gemm_async_core(sm, A, lda, B, ldb, C, ldc, K,
                    blockIdx.y * 128, blockIdx.x * 128, 0, 1 << 30, 0);
}

__global__ void __launch_bounds__(256) gemm_rkv_async()
{
    extern __shared__ float sm[];
    const int p  = blockIdx.x >> 3;
    const int n0 = (blockIdx.x & 7) * 128;
    const float* A = g_buf + ((p == 0) ? OFF_XR : (p == 1) ? OFF_XK : OFF_XV);
    const float* B = g_buf + OFF_WB + ((size_t)p << 20);
    float* C = g_buf + OFF_R + (size_t)p * SZ;
    gemm_async_core(sm, A, CH, B, CH, C, CH, CH,
                    blockIdx.y * 128, n0, 0, 1 << 30, 0);
}

__global__ void __launch_bounds__(256) gemm_dn_async(int zbase)
{
    extern __shared__ float sm[];
    const int z = zbase + blockIdx.z;
    const int koff = (z == 0) ? 0 : (z == 1) ? 64 : (z == 2) ? 128 : 192;
    const int Kz   = (z == 0) ? 64 : (z == 1) ? 64 : (z == 2) ? 32 : 160;
    const float* A = g_buf + OFF_H + koff;
    const float* B = g_buf + OFF_WDNT + koff;
    float* C = g_buf + OFF_TW + (size_t)z * SZ;
    gemm_async_core(sm, A, NUP, B, NUP, C, CH, Kz,
                    blockIdx.y * 128, blockIdx.x * 128, 0, 1 << 30, 0);
}

// LoRA up-projection, split-K2, permuted epilogue (R9 config)
__global__ void __launch_bounds__(256) gemm_up_async()
{
    extern __shared__ float sm[];
    const int tile = blockIdx.x;
    const int kz   = blockIdx.z;
    const int seg  = (tile <= 3) ? tile : 3;
    const int brow = seg * 128 + ((tile == 4) ? 128 : 0);
    const int coff = (tile == 0) ? 0 : (tile == 1) ? 64 : (tile == 2) ? 128 :
                     (tile == 3) ? 192 : 320;
    const int wid  = (tile == 0) ? 64 : (tile == 1) ? 64 : (tile == 2) ? 32 :
                     (tile == 3) ? 128 : 32;
    const size_t aoff = (seg == 0) ? OFF_XW : (seg == 1) ? OFF_XA :
                        (seg == 2) ? OFF_XV : OFF_XG;
    const float* A = g_buf + aoff + (size_t)kz * 512;
    const float* B = g_buf + OFF_WUPT + (size_t)brow * 1024 + (size_t)kz * 512;
    float* C = g_buf + (kz ? OFF_H1 : OFF_H);
    gemm_async_core(sm, A, CH, B, 1024, C, NUP, 512,
                    blockIdx.y * 128, 0, coff, wid, 1);
}

__global__ void __launch_bounds__(256) combine_up_kernel()
{
    int idx = blockIdx.x * 256 + threadIdx.x;    // < TOK*NUP
    float h = g_buf[OFF_H + idx] + g_buf[OFF_H1 + idx];
    int col = idx % NUP;
    if (col < 64)                     h = tanhf(h);
    else if (col >= 192 && col < 352) h = 1.f / (1.f + expf(-h));
    g_buf[OFF_H + idx] = rtf32(h);
}

// ---------------------------------------------------------------------------
// recurrence v3: ew fused. 128 CTAs (2 per (b,h), 32 rows each), 128 threads.
// Stages RAW r/tw/k/v/ta/tv/vfirst per 16-step chunk, transforms in-place
// (decay, a-sigmoid, v-residual, kk-normalize, kn), then runs the recurrence.
// half==0 CTA also streams kn/nv to OFF_KN/OFF_NV for post's bonus term.
// ---------------------------------------------------------------------------
__global__ void __launch_bounds__(128) rec_kernel(
    const float* __restrict__ v_first,
    const float* __restrict__ w0, const float* __restrict__ a0,
    const float* __restrict__ v0p, const float* __restrict__ k_k,
    const float* __restrict__ k_a)
{
    extern __shared__ float smrec[];
    // layout: [2][7][16][64]; arrays: 0:r 1:tw->wdec 2:k->kn' 3:v->nv 4:ta->akk 5:tv->bkk 6:vf
    auto SH = [&](int bufi, int arr, int st) -> float* {
        return smrec + (((bufi * 7 + arr) * 16 + st) << 6);
    };

    const int bh   = blockIdx.x >> 1;
    const int half = blockIdx.x & 1;
    const int b  = bh >> 4;
    const int h  = bh & 15;
    const int tid = threadIdx.x;
    const int rg  = tid >> 3;           // 0..15 (row-pair in compute; timestep in transform)
    const int q   = tid & 7;            // col octet
    const int i0  = half * 32 + rg * 2;
    const int j0  = q * 8;

    const size_t base = ((size_t)b * 1024) * CH + (size_t)h * HS;
    const float* srcs[7] = {
        g_buf + OFF_R  + base, g_buf + OFF_TW + base,
        g_buf + OFF_K  + base, g_buf + OFF_V  + base,
        g_buf + OFF_TA + base, g_buf + OFF_TV + base,
        v_first + base };
    float* py  = g_buf + OFF_Y  + base;
    float* pkn = g_buf + OFF_KN + base;
    float* pnv = g_buf + OFF_NV + base;

    // per-thread channel constants (8 channels j0..j0+7 of head h)
    const int ch = h * HS + j0;
    float w0r[8], a0r[8], v0r[8], kkr[8], kar[8];
#pragma unroll
    for (int j = 0; j < 8; j++) {
        w0r[j] = w0[ch + j];  a0r[j] = a0[ch + j];  v0r[j] = v0p[ch + j];
        kkr[j] = k_k[ch + j]; kar[j] = k_a[ch + j];
    }

    const uint32_t shaddr = (uint32_t)__cvta_generic_to_shared(smrec);

    auto load_chunk = [&](int bufi, int t0) {
#pragma unroll
        for (int r = 0; r < 14; r++) {
            int idx = tid + 128 * r;          // < 1792
            int arr = idx >> 8;
            int rem = idx & 255;
            int st  = rem >> 4;
            int grp = rem & 15;
            uint32_t dst = shaddr + (uint32_t)((((bufi * 7 + arr) * 16 + st) << 6) + grp * 4) * 4;
            cp16(dst, srcs[arr] + (size_t)(t0 + st) * CH + grp * 4);
        }
        asm volatile("cp.async.commit_group;" ::: "memory");
    };

    // per-chunk ew transform (thread = one timestep x 8 channels), in-place
    auto transform = [&](int bufi, int t0) {
        const int st = rg;                 // timestep within chunk
        float tw[8], kr[8], vv[8], ta[8], tv[8], vf[8];
        *(float4*)&tw[0] = *(const float4*)(SH(bufi,1,st) + j0);
        *(float4*)&tw[4] = *(const float4*)(SH(bufi,1,st) + j0 + 4);
        *(float4*)&kr[0] = *(const float4*)(SH(bufi,2,st) + j0);
        *(float4*)&kr[4] = *(const float4*)(SH(bufi,2,st) + j0 + 4);
        *(float4*)&vv[0] = *(const float4*)(SH(bufi,3,st) + j0);
        *(float4*)&vv[4] = *(const float4*)(SH(bufi,3,st) + j0 + 4);
        *(float4*)&ta[0] = *(const float4*)(SH(bufi,4,st) + j0);
        *(float4*)&ta[4] = *(const float4*)(SH(bufi,4,st) + j0 + 4);
        *(float4*)&tv[0] = *(const float4*)(SH(bufi,5,st) + j0);
        *(float4*)&tv[4] = *(const float4*)(SH(bufi,5,st) + j0 + 4);
        *(float4*)&vf[0] = *(const float4*)(SH(bufi,6,st) + j0);
        *(float4*)&vf[4] = *(const float4*)(SH(bufi,6,st) + j0 + 4);

        float wd[8], aa[8], kkv[8], kn[8], nv[8];
        float ss = 0.f;
#pragma unroll
        for (int j = 0; j < 8; j++) {
            float z = -w0r[j] - tw[j];
            float sp = (z > 20.f) ? z : log1pf(expf(z));
            wd[j] = expf(-expf(-sp - 0.5f));
            aa[j] = 1.f / (1.f + expf(-(a0r[j] + ta[j])));
            float sv = 1.f / (1.f + expf(-(v0r[j] + tv[j])));
            nv[j] = vv[j] + (vf[j] - vv[j]) * sv;
            kkv[j] = kr[j] * kkr[j];
            kn[j] = kr[j] * (1.f + (aa[j] - 1.f) * kar[j]);
            ss = fmaf(kkv[j], kkv[j], ss);
        }
#pragma unroll
        for (int m = 1; m <= 4; m <<= 1) ss += __shfl_xor_sync(0xffffffffu, ss, m);
        float inv = 1.f / fmaxf(sqrtf(ss), 1e-12f);
        float ak[8], bk[8];
#pragma unroll
        for (int j = 0; j < 8; j++) {
            ak[j] = kkv[j] * inv;
            bk[j] = -ak[j] * aa[j];
        }
        // write back: 1<-wd, 2<-kn, 3<-nv, 4<-ak, 5<-bk
        *(float4*)(SH(bufi,1,st) + j0)     = *(const float4*)&wd[0];
        *(float4*)(SH(bufi,1,st) + j0 + 4) = *(const float4*)&wd[4];
        *(float4*)(SH(bufi,2,st) + j0)     = *(const float4*)&kn[0];
        *(float4*)(SH(bufi,2,st) + j0 + 4) = *(const float4*)&kn[4];
        *(float4*)(SH(bufi,3,st) + j0)     = *(const float4*)&nv[0];
        *(float4*)(SH(bufi,3,st) + j0 + 4) = *(const float4*)&nv[4];
        *(float4*)(SH(bufi,4,st) + j0)     = *(const float4*)&ak[0];
        *(float4*)(SH(bufi,4,st) + j0 + 4) = *(const float4*)&ak[4];
        *(float4*)(SH(bufi,5,st) + j0)     = *(const float4*)&bk[0];
        *(float4*)(SH(bufi,5,st) + j0 + 4) = *(const float4*)&bk[4];
        if (half == 0) {
            size_t g = (size_t)(t0 + st) * CH + j0;
            *(float4*)(pkn + g)     = *(const float4*)&kn[0];
            *(float4*)(pkn + g + 4) = *(const float4*)&kn[4];
            *(float4*)(pnv + g)     = *(const float4*)&nv[0];
            *(float4*)(pnv + g + 4) = *(const float4*)&nv[4];
        }
    };

    float s0[8], s1[8];
#pragma unroll
    for (int jj = 0; jj < 8; jj++) { s0[jj] = 0.f; s1[jj] = 0.f; }

    load_chunk(0, 0);
    asm volatile("cp.async.wait_group 0;" ::: "memory");
    __syncthreads();
    transform(0, 0);
    __syncthreads();

    int cur = 0;
    for (int t0 = 0; t0 < 1024; t0 += 16) {
        if (t0 + 16 < 1024) load_chunk(cur ^ 1, t0 + 16);

#pragma unroll 4
        for (int tt = 0; tt < 16; tt++) {
            const float* ra = SH(cur, 4, tt);
            float4 a4a = *(const float4*)(ra + j0);
            float4 a4b = *(const float4*)(ra + j0 + 4);
            float a_[8] = {a4a.x, a4a.y, a4a.z, a4a.w, a4b.x, a4b.y, a4b.z, a4b.w};

            float p00 = fmaf(s0[0], a_[0], fmaf(s0[2], a_[2], fmaf(s0[4], a_[4], s0[6] * a_[6])));
            float p01 = fmaf(s0[1], a_[1], fmaf(s0[3], a_[3], fmaf(s0[5], a_[5], s0[7] * a_[7])));
            float p10 = fmaf(s1[0], a_[0], fmaf(s1[2], a_[2], fmaf(s1[4], a_[4], s1[6] * a_[6])));
            float p11 = fmaf(s1[1], a_[1], fmaf(s1[3], a_[3], fmaf(s1[5], a_[5], s1[7] * a_[7])));
            float sa0 = p00 + p01;
            float sa1 = p10 + p11;
#pragma unroll
            for (int m = 1; m <= 4; m <<= 1) {
                sa0 += __shfl_xor_sync(0xffffffffu, sa0, m);
                sa1 += __shfl_xor_sync(0xffffffffu, sa1, m);
            }

            float2 v2 = *(const float2*)(SH(cur, 3, tt) + i0);

            float4 w4a = *(const float4*)(SH(cur,1,tt) + j0);
            float4 w4b = *(const float4*)(SH(cur,1,tt) + j0 + 4);
            float4 k4a = *(const float4*)(SH(cur,2,tt) + j0);
            float4 k4b = *(const float4*)(SH(cur,2,tt) + j0 + 4);
            float4 b4a = *(const float4*)(SH(cur,5,tt) + j0);
            float4 b4b = *(const float4*)(SH(cur,5,tt) + j0 + 4);
            float4 r4a = *(const float4*)(SH(cur,0,tt) + j0);
            float4 r4b = *(const float4*)(SH(cur,0,tt) + j0 + 4);
            float w_[8] = {w4a.x, w4a.y, w4a.z, w4a.w, w4b.x, w4b.y, w4b.z, w4b.w};
            float k_[8] = {k4a.x, k4a.y, k4a.z, k4a.w, k4b.x, k4b.y, k4b.z, k4b.w};
            float b_[8] = {b4a.x, b4a.y, b4a.z, b4a.w, b4b.x, b4b.y, b4b.z, b4b.w};
            float r_[8] = {r4a.x, r4a.y, r4a.z, r4a.w, r4b.x, r4b.y, r4b.z, r4b.w};

            float y0a = 0.f, y0b = 0.f, y1a = 0.f, y1b = 0.f;
#pragma unroll
            for (int jj = 0; jj < 8; jj++) {
                float ns0 = fmaf(sa0, b_[jj], fmaf(v2.x, k_[jj], s0[jj] * w_[jj]));
                float ns1 = fmaf(sa1, b_[jj], fmaf(v2.y, k_[jj], s1[jj] * w_[jj]));
                s0[jj] = ns0; s1[jj] = ns1;
                if (jj & 1) { y0b = fmaf(ns0, r_[jj], y0b); y1b = fmaf(ns1, r_[jj], y1b); }
                else        { y0a = fmaf(ns0, r_[jj], y0a); y1a = fmaf(ns1, r_[jj], y1a); }
            }
            float y0 = y0a + y0b, y1 = y1a + y1b;
#pragma unroll
            for (int m = 1; m <= 4; m <<= 1) {
                y0 += __shfl_xor_sync(0xffffffffu, y0, m);
                y1 += __shfl_xor_sync(0xffffffffu, y1, m);
            }
            if (q == 0)
                *(float2*)(py + (size_t)(t0 + tt) * CH + i0) = make_float2(y0, y1);
        }

        asm volatile("cp.async.wait_group 0;" ::: "memory");
        __syncthreads();
        if (t0 + 16 < 1024) {
            transform(cur ^ 1, t0 + 16);
            __syncthreads();
        }
        cur ^= 1;
    }
}

// ---------------------------------------------------------------------------
// GroupNorm + bonus + gate (reads rec-computed kn/nv; k-permuted tf32 store)
// ---------------------------------------------------------------------------
__global__ void __launch_bounds__(256) post_kernel(
    const float* __restrict__ r_k,
    const float* __restrict__ gn_w, const float* __restrict__ gn_b)
{
    int wid  = blockIdx.x * 8 + (threadIdx.x >> 5);
    int lane = threadIdx.x & 31;
    int t = wid >> 4;
    int h = wid & 15;
    int c0 = h * HS + lane * 2;
    size_t base = (size_t)t * CH + c0;

    float2 yv = *(const float2*)(g_buf + OFF_Y + base);
    float2 rv = *(const float2*)(g_buf + OFF_R + base);
    float2 kv = *(const float2*)(g_buf + OFF_KN + base);
    float2 vv = *(const float2*)(g_buf + OFF_NV + base);
    float2 gv = *(const float2*)(g_buf + OFF_GATE + base);
    float2 rk = *(const float2*)(r_k + c0);

    float s1 = yv.x + yv.y;
    float s2 = yv.x * yv.x + yv.y * yv.y;
    float s3 = rv.x * kv.x * rk.x + rv.y * kv.y * rk.y;
#pragma unroll
    for (int m = 16; m; m >>= 1) {
        s1 += __shfl_xor_sync(0xffffffffu, s1, m);
        s2 += __shfl_xor_sync(0xffffffffu, s2, m);
        s3 += __shfl_xor_sync(0xffffffffu, s3, m);
    }
    float mu  = s1 * (1.f / 64.f);
    float var = s2 * (1.f / 64.f) - mu * mu;
    float rstd = rsqrtf(var + 0.00064f);

    float2 gw = *(const float2*)(gn_w + c0);
    float2 gb = *(const float2*)(gn_b + c0);
    float o0 = (fmaf((yv.x - mu) * rstd, gw.x, gb.x) + s3 * vv.x) * gv.x;
    float o1 = (fmaf((yv.y - mu) * rstd, gw.y, gb.y) + s3 * vv.y) * gv.y;
    size_t rowb = (size_t)t * CH;
    g_buf[OFF_YP + rowb + pcol(c0)]     = rtf32(o0);
    g_buf[OFF_YP + rowb + pcol(c0 + 1)] = rtf32(o1);
}

// ---------------------------------------------------------------------------
extern "C" void kernel_launch(void* const* d_in, const int* in_sizes, int n_in,
                              void* d_out, int out_size)
{
    (void)in_sizes; (void)n_in; (void)out_size;
    float* buf = nullptr;
    cudaGetSymbolAddress((void**)&buf, g_buf);

    static cudaStream_t s1 = nullptr;
    static cudaEvent_t evFork = nullptr, evPacks = nullptr, evMix = nullptr,
                       evDnW = nullptr, evDnG = nullptr;
    if (s1 == nullptr) {
        cudaStreamCreateWithFlags(&s1, cudaStreamNonBlocking);
        cudaEventCreateWithFlags(&evFork,  cudaEventDisableTiming);
        cudaEventCreateWithFlags(&evPacks, cudaEventDisableTiming);
        cudaEventCreateWithFlags(&evMix,   cudaEventDisableTiming);
        cudaEventCreateWithFlags(&evDnW,   cudaEventDisableTiming);
        cudaEventCreateWithFlags(&evDnG,   cudaEventDisableTiming);
        cudaFuncSetAttribute(gemm_nt_async,  cudaFuncAttributeMaxDynamicSharedMemorySize, SMEM_BYTES);
        cudaFuncSetAttribute(gemm_rkv_async, cudaFuncAttributeMaxDynamicSharedMemorySize, SMEM_BYTES);
        cudaFuncSetAttribute(gemm_dn_async,  cudaFuncAttributeMaxDynamicSharedMemorySize, SMEM_BYTES);
        cudaFuncSetAttribute(gemm_up_async,  cudaFuncAttributeMaxDynamicSharedMemorySize, SMEM_BYTES);
        cudaFuncSetAttribute(rec_kernel,     cudaFuncAttributeMaxDynamicSharedMemorySize, REC_SMEM);
    }

    const float* x    = (const float*)d_in[0];
    const float* vfir = (const float*)d_in[1];
    const float* x_r  = (const float*)d_in[2];
    const float* x_w  = (const float*)d_in[3];
    const float* x_k  = (const float*)d_in[4];
    const float* x_v  = (const float*)d_in[5];
    const float* x_a  = (const float*)d_in[6];
    const float* x_g  = (const float*)d_in[7];
    const float* w0   = (const float*)d_in[8];
    const float* w1   = (const float*)d_in[9];
    const float* w2   = (const float*)d_in[10];
    const float* a0   = (const float*)d_in[11];
    const float* a1   = (const float*)d_in[12];
    const float* a2   = (const float*)d_in[13];
    const float* v0p  = (const float*)d_in[14];
    const float* v1   = (const float*)d_in[15];
    const float* v2   = (const float*)d_in[16];
    const float* g1   = (const float*)d_in[17];
    const float* g2   = (const float*)d_in[18];
    const float* k_k  = (const float*)d_in[19];
    const float* k_a  = (const float*)d_in[20];
    const float* r_k  = (const float*)d_in[21];
    const float* W_r  = (const float*)d_in[22];
    const float* W_k  = (const float*)d_in[23];
    const float* W_v  = (const float*)d_in[24];
    const float* W_o  = (const float*)d_in[25];
    const float* gn_w = (const float*)d_in[26];
    const float* gn_b = (const float*)d_in[27];
    float* out = (float*)d_out;

    // ---- fork side stream ----
    cudaEventRecord(evFork, 0);
    cudaStreamWaitEvent(s1, evFork, 0);

    // s1: weight packs
    pack_rkvo_kernel<<<(4 << 20) / 256, 256, 0, s1>>>(W_r, W_k, W_v, W_o);
    pack_up_kernel<<<(640 * 1024 + 255) / 256, 256, 0, s1>>>(w1, a1, v1, g1);
    pack_dn_kernel<<<(1024 * NUP + 255) / 256, 256, 0, s1>>>(w2, a2, v2, g2);
    cudaEventRecord(evPacks, s1);

    // s0: mixes, then r/k/v
    mix_kernel<<<(int)(SZ / 256), 256>>>(x, x_r, x_w, x_k, x_v, x_a, x_g);
    cudaEventRecord(evMix, 0);
    cudaStreamWaitEvent(0, evPacks, 0);
    gemm_rkv_async<<<dim3(24, TOK / 128), 256, SMEM_BYTES>>>();

    // s1: LoRA chain (split-K up + combine, then downs)
    cudaStreamWaitEvent(s1, evMix, 0);
    gemm_up_async<<<dim3(5, TOK / 128, 2), 256, SMEM_BYTES, s1>>>();
    combine_up_kernel<<<TOK * NUP / 256, 256, 0, s1>>>();
    gemm_dn_async<<<dim3(CH / 128, TOK / 128, 3), 256, SMEM_BYTES, s1>>>(0);  // w,a,v
    cudaEventRecord(evDnW, s1);
    gemm_dn_async<<<dim3(CH / 128, TOK / 128, 1), 256, SMEM_BYTES, s1>>>(3);  // gate
    cudaEventRecord(evDnG, s1);

    // s0: recurrence (ew fused) after rkv + dn w/a/v
    cudaStreamWaitEvent(0, evDnW, 0);
    rec_kernel<<<128, 128, REC_SMEM>>>(vfir, w0, a0, v0p, k_k, k_a);

    // s0: join gate, post + Wo
    cudaStreamWaitEvent(0, evDnG, 0);
    post_kernel<<<TOK * NH / 8, 256>>>(r_k, gn_w, gn_b);
    gemm_nt_async<<<dim3(CH / 128, TOK / 128), 256, SMEM_BYTES>>>(
        buf + OFF_YP, CH, buf + OFF_WB + (3u << 20), CH, out, CH, CH);
}

// round 12
// speedup vs baseline: 1.1589x; 1.1589x over previous
#include <cuda_runtime.h>
#include <math.h>
#include <stdint.h>

#define TOK 4096          // B*T
#define CH  1024          // C
#define NH  16            // heads
#define HS  64            // head size
#define NUP 384           // packed LoRA hidden width
#define STAGES 3
#define ROWW 24           // smem row stride in words (16 data + 8 pad; conflict-free LDS.64)
#define MATW (STAGES * 128 * ROWW)          // words per matrix buffer
#define SMEM_BYTES (2 * MATW * 4)           // 73728 B dynamic smem

static constexpr size_t SZ = (size_t)TOK * CH;

static constexpr size_t OFF_XR   = 0 * SZ;
static constexpr size_t OFF_XW   = 1 * SZ;
static constexpr size_t OFF_XK   = 2 * SZ;
static constexpr size_t OFF_XV   = 3 * SZ;
static constexpr size_t OFF_XA   = 4 * SZ;
static constexpr size_t OFF_XG   = 5 * SZ;
static constexpr size_t OFF_R    = 6 * SZ;   // R,K,V contiguous
static constexpr size_t OFF_K    = 7 * SZ;
static constexpr size_t OFF_V    = 8 * SZ;
static constexpr size_t OFF_TW   = 9 * SZ;   // TW,TA,TV,GATE contiguous
static constexpr size_t OFF_TA   = 10 * SZ;
static constexpr size_t OFF_TV   = 11 * SZ;
static constexpr size_t OFF_GATE = 12 * SZ;
static constexpr size_t OFF_WDEC = 13 * SZ;
static constexpr size_t OFF_AKK  = 14 * SZ;
static constexpr size_t OFF_BKK  = 15 * SZ;
static constexpr size_t OFF_Y    = 16 * SZ;
static constexpr size_t OFF_YP   = 17 * SZ;
static constexpr size_t OFF_H    = 18 * SZ;                          // [TOK][384] (k-permuted cols)
static constexpr size_t OFF_H1   = 18 * SZ + (size_t)TOK * NUP;      // split-K partial
static constexpr size_t OFF_WUPT = 19 * SZ;                          // [640][1024] n-major (tf32, k-perm)
static constexpr size_t OFF_WDNT = 19 * SZ + (size_t)640 * 1024;     // [1024][384] n-major (tf32, k-perm)
static constexpr size_t OFF_WB   = 20 * SZ;                          // Wr|Wk|Wv|Wo tf32 (k-perm), 1M each
static constexpr size_t TOTALF   = 21 * SZ;

__device__ float g_buf[TOTALF];

__device__ __forceinline__ float rtf32(float f) {
    uint32_t u; asm("cvt.rna.tf32.f32 %0, %1;" : "=r"(u) : "f"(f));
    return __uint_as_float(u);
}

// k-permutation within each 8-group: P(k) = (k&~7) | ((k&3)<<1) | ((k>>2)&1)
__device__ __forceinline__ int pcol(int k) {
    return (k & ~7) | ((k & 3) << 1) | ((k >> 2) & 1);
}

__device__ __forceinline__ void cp16(uint32_t dst, const float* src) {
    asm volatile("cp.async.cg.shared.global [%0], [%1], 16;" :: "r"(dst), "l"(src));
}

// packed f32x2 math (sm_100+): per-lane IEEE fma/mul, bit-identical to scalar
__device__ __forceinline__ float2 f2mul(float2 a, float2 b) {
    unsigned long long ra = *(unsigned long long*)&a;
    unsigned long long rb = *(unsigned long long*)&b;
    unsigned long long rd;
    asm("mul.rn.f32x2 %0, %1, %2;" : "=l"(rd) : "l"(ra), "l"(rb));
    return *(float2*)&rd;
}
__device__ __forceinline__ float2 f2fma(float2 a, float2 b, float2 c) {
    unsigned long long ra = *(unsigned long long*)&a;
    unsigned long long rb = *(unsigned long long*)&b;
    unsigned long long rc = *(unsigned long long*)&c;
    unsigned long long rd;
    asm("fma.rn.f32x2 %0, %1, %2, %3;" : "=l"(rd) : "l"(ra), "l"(rb), "l"(rc));
    return *(float2*)&rd;
}

// ---------------------------------------------------------------------------
// 1) token-shift mixes (tf32-rounded, k-permuted: feed GEMMs only)
// ---------------------------------------------------------------------------
__global__ void __launch_bounds__(256) mix_kernel(
    const float* __restrict__ x,
    const float* __restrict__ mr, const float* __restrict__ mw,
    const float* __restrict__ mk, const float* __restrict__ mv,
    const float* __restrict__ ma, const float* __restrict__ mg)
{
    int idx = blockIdx.x * 256 + threadIdx.x;
    int c   = idx & (CH - 1);
    int row = idx >> 10;
    int t   = row & 1023;
    float xv = x[idx];
    float lx = (t == 0) ? 0.f : x[idx - CH];
    float dx = lx - xv;
    size_t w = (size_t)row * CH + pcol(c);
    g_buf[OFF_XR + w] = rtf32(fmaf(mr[c], dx, xv));
    g_buf[OFF_XW + w] = rtf32(fmaf(mw[c], dx, xv));
    g_buf[OFF_XK + w] = rtf32(fmaf(mk[c], dx, xv));
    g_buf[OFF_XV + w] = rtf32(fmaf(mv[c], dx, xv));
    g_buf[OFF_XA + w] = rtf32(fmaf(ma[c], dx, xv));
    g_buf[OFF_XG + w] = rtf32(fmaf(mg[c], dx, xv));
}

// ---------------------------------------------------------------------------
// weight packs (tf32-rounded, k-permuted)
// ---------------------------------------------------------------------------
__global__ void __launch_bounds__(256) pack_up_kernel(
    const float* __restrict__ w1, const float* __restrict__ a1,
    const float* __restrict__ v1, const float* __restrict__ g1)
{
    int idx = blockIdx.x * 256 + threadIdx.x;   // < 640*1024
    if (idx >= 640 * 1024) return;
    int n = idx >> 10;
    int k = idx & 1023;
    float v = 0.f;
    if      (n < 64)                 v = w1[k * 64  + n];
    else if (n >= 128 && n < 192)    v = a1[k * 64  + (n - 128)];
    else if (n >= 256 && n < 288)    v = v1[k * 32  + (n - 256)];
    else if (n >= 384 && n < 544)    v = g1[k * 160 + (n - 384)];
    g_buf[OFF_WUPT + ((size_t)n << 10) + pcol(k)] = rtf32(v);
}

__global__ void __launch_bounds__(256) pack_dn_kernel(
    const float* __restrict__ w2, const float* __restrict__ a2,
    const float* __restrict__ v2, const float* __restrict__ g2)
{
    int idx = blockIdx.x * 256 + threadIdx.x;       // < 1024*384
    if (idx >= 1024 * NUP) return;
    int n  = idx / NUP;
    int kk = idx - n * NUP;
    float v;
    if      (kk < 64)  v = w2[(size_t)kk * 1024 + n];
    else if (kk < 128) v = a2[(size_t)(kk - 64) * 1024 + n];
    else if (kk < 160) v = v2[(size_t)(kk - 128) * 1024 + n];
    else if (kk < 192) v = 0.f;
    else if (kk < 352) v = g2[(size_t)(kk - 192) * 1024 + n];
    else               v = 0.f;
    g_buf[OFF_WDNT + (size_t)n * NUP + pcol(kk)] = rtf32(v);
}

__global__ void __launch_bounds__(256) pack_rkvo_kernel(
    const float* __restrict__ Wr, const float* __restrict__ Wk,
    const float* __restrict__ Wv, const float* __restrict__ Wo)
{
    int idx = blockIdx.x * 256 + threadIdx.x;   // < 4*1M
    int m = idx >> 20;
    int e = idx & ((1 << 20) - 1);
    int n = e >> 10;
    int k = e & 1023;
    const float* src = (m == 0) ? Wr : (m == 1) ? Wk : (m == 2) ? Wv : Wo;
    g_buf[OFF_WB + ((size_t)m << 20) + ((size_t)n << 10) + pcol(k)] = rtf32(src[e]);
}

// ---------------------------------------------------------------------------
// tf32 MMA core, cp.async 3-stage pipeline (NT), k-permuted inputs (R9 config).
// ---------------------------------------------------------------------------
__device__ __forceinline__ void gemm_async_core(
    float* sm, const float* A, int lda, const float* B, int ldb,
    float* C, int ldc, int K, int m0, int n0, int col_off, int width, int permout)
{
    const int tid  = threadIdx.x;
    const int lane = tid & 31, warp = tid >> 5;
    const int wm = warp >> 2, wn = warp & 3;

    float* smA = sm;
    float* smB = sm + MATW;
    const uint32_t saA = (uint32_t)__cvta_generic_to_shared(smA);
    const uint32_t saB = (uint32_t)__cvta_generic_to_shared(smB);

    const int rowc = tid >> 1;
    const int jj4  = (tid & 1) * 8;
    const float* Abase = A + (size_t)(m0 + rowc) * lda + jj4;
    const float* Bbase = B + (size_t)(n0 + rowc) * ldb + jj4;
    const uint32_t soff = (uint32_t)((rowc * ROWW + jj4) * 4);

    float acc[4][4][4];
#pragma unroll
    for (int mt = 0; mt < 4; mt++)
#pragma unroll
        for (int nt = 0; nt < 4; nt++)
#pragma unroll
            for (int r = 0; r < 4; r++) acc[mt][nt][r] = 0.f;

    auto issue = [&](int s, int k0) {
        uint32_t da = saA + (uint32_t)(s * 128 * ROWW * 4) + soff;
        uint32_t db = saB + (uint32_t)(s * 128 * ROWW * 4) + soff;
        cp16(da,      Abase + k0);
        cp16(da + 16, Abase + k0 + 4);
        cp16(db,      Bbase + k0);
        cp16(db + 16, Bbase + k0 + 4);
    };

#pragma unroll
    for (int s = 0; s < STAGES - 1; s++) {
        if (s * 16 < K) issue(s, s * 16);
        asm volatile("cp.async.commit_group;" ::: "memory");
    }

    const int q2 = (lane & 3) * 2;

    int stage = 0;
    for (int k0 = 0; k0 < K; k0 += 16) {
        asm volatile("cp.async.wait_group 1;" ::: "memory");
        __syncthreads();
        int kn = k0 + (STAGES - 1) * 16;
        if (kn < K) {
            int sn = stage + (STAGES - 1); if (sn >= STAGES) sn -= STAGES;
            issue(sn, kn);
        }
        asm volatile("cp.async.commit_group;" ::: "memory");

        const float* As = smA + stage * 128 * ROWW;
        const float* Bs = smB + stage * 128 * ROWW;
#pragma unroll
        for (int kk = 0; kk < 2; kk++) {
            const int base = kk * 8 + q2;
            uint2 ap0[4], ap1[4], bp[4];
#pragma unroll
            for (int mt = 0; mt < 4; mt++) {
                int r = wm * 64 + mt * 16 + (lane >> 2);
                ap0[mt] = *(const uint2*)&As[r * ROWW + base];        // (c, c+4)
                ap1[mt] = *(const uint2*)&As[(r + 8) * ROWW + base];
            }
#pragma unroll
            for (int nt = 0; nt < 4; nt++) {
                int n = wn * 32 + nt * 8 + (lane >> 2);
                bp[nt] = *(const uint2*)&Bs[n * ROWW + base];
            }
#pragma unroll
            for (int mt = 0; mt < 4; mt++)
#pragma unroll
                for (int nt = 0; nt < 4; nt++) {
                    asm volatile(
                        "mma.sync.aligned.m16n8k8.row.col.f32.tf32.tf32.f32 "
                        "{%0,%1,%2,%3},{%4,%5,%6,%7},{%8,%9},{%0,%1,%2,%3};"
                        : "+f"(acc[mt][nt][0]), "+f"(acc[mt][nt][1]),
                          "+f"(acc[mt][nt][2]), "+f"(acc[mt][nt][3])
                        : "r"(ap0[mt].x), "r"(ap1[mt].x),
                          "r"(ap0[mt].y), "r"(ap1[mt].y),
                          "r"(bp[nt].x), "r"(bp[nt].y));
                }
        }
        stage = (stage + 1 == STAGES) ? 0 : stage + 1;
    }

#pragma unroll
    for (int mt = 0; mt < 4; mt++) {
        int row = m0 + wm * 64 + mt * 16 + (lane >> 2);
#pragma unroll
        for (int nt = 0; nt < 4; nt++) {
            int col = wn * 32 + nt * 8 + (lane & 3) * 2;
            if (col < width) {
                if (permout) {
                    int p0 = pcol(n0 + col), p1 = pcol(n0 + col + 1);
                    C[(size_t)row * ldc + col_off + p0] = acc[mt][nt][0];
                    C[(size_t)row * ldc + col_off + p1] = acc[mt][nt][1];
                    C[(size_t)(row + 8) * ldc + col_off + p0] = acc[mt][nt][2];
                    C[(size_t)(row + 8) * ldc + col_off + p1] = acc[mt][nt][3];
                } else {
                    int gcol = n0 + col;
                    *(float2*)(C + (size_t)row * ldc + col_off + gcol) =
                        make_float2(acc[mt][nt][0], acc[mt][nt][1]);
                    *(float2*)(C + (size_t)(row + 8) * ldc + col_off + gcol) =
                        make_float2(acc[mt][nt][2], acc[mt][nt][3]);
                }
            }
        }
    }
}

__global__ void __launch_bounds__(256) gemm_nt_async(
    const float* __restrict__ A, int lda,
    const float* __restrict__ B, int ldb,
    float* __restrict__ C, int ldc, int K)
{
    extern __shared__ float sm[];
    gemm_async_core(sm, A, lda, B, ldb, C, ldc, K,
                    blockIdx.y * 128, blockIdx.x * 128, 0, 1 << 30, 0);
}

__global__ void __launch_bounds__(256) gemm_rkv_async()
{
    extern __shared__ float sm[];
    const int p  = blockIdx.x >> 3;
    const int n0 = (blockIdx.x & 7) * 128;
    const float* A = g_buf + ((p == 0) ? OFF_XR : (p == 1) ? OFF_XK : OFF_XV);
    const float* B = g_buf + OFF_WB + ((size_t)p << 20);
    float* C = g_buf + OFF_R + (size_t)p * SZ;
    gemm_async_core(sm, A, CH, B, CH, C, CH, CH,
                    blockIdx.y * 128, n0, 0, 1 << 30, 0);
}

__global__ void __launch_bounds__(256) gemm_dn_async(int zbase)
{
    extern __shared__ float sm[];
    const int z = zbase + blockIdx.z;
    const int koff = (z == 0) ? 0 : (z == 1) ? 64 : (z == 2) ? 128 : 192;
    const int Kz   = (z == 0) ? 64 : (z == 1) ? 64 : (z == 2) ? 32 : 160;
    const float* A = g_buf + OFF_H + koff;
    const float* B = g_buf + OFF_WDNT + koff;
    float* C = g_buf + OFF_TW + (size_t)z * SZ;
    gemm_async_core(sm, A, NUP, B, NUP, C, CH, Kz,
                    blockIdx.y * 128, blockIdx.x * 128, 0, 1 << 30, 0);
}

// LoRA up-projection, split-K2, permuted epilogue (R9 config)
__global__ void __launch_bounds__(256) gemm_up_async()
{
    extern __shared__ float sm[];
    const int tile = blockIdx.x;
    const int kz   = blockIdx.z;
    const int seg  = (tile <= 3) ? tile : 3;
    const int brow = seg * 128 + ((tile == 4) ? 128 : 0);
    const int coff = (tile == 0) ? 0 : (tile == 1) ? 64 : (tile == 2) ? 128 :
                     (tile == 3) ? 192 : 320;
    const int wid  = (tile == 0) ? 64 : (tile == 1) ? 64 : (tile == 2) ? 32 :
                     (tile == 3) ? 128 : 32;
    const size_t aoff = (seg == 0) ? OFF_XW : (seg == 1) ? OFF_XA :
                        (seg == 2) ? OFF_XV : OFF_XG;
    const float* A = g_buf + aoff + (size_t)kz * 512;
    const float* B = g_buf + OFF_WUPT + (size_t)brow * 1024 + (size_t)kz * 512;
    float* C = g_buf + (kz ? OFF_H1 : OFF_H);
    gemm_async_core(sm, A, CH, B, 1024, C, NUP, 512,
                    blockIdx.y * 128, 0, coff, wid, 1);
}

__global__ void __launch_bounds__(256) combine_up_kernel()
{
    int idx = blockIdx.x * 256 + threadIdx.x;    // < TOK*NUP
    float h = g_buf[OFF_H + idx] + g_buf[OFF_H1 + idx];
    int col = idx % NUP;
    if (col < 64)                     h = tanhf(h);
    else if (col >= 192 && col < 352) h = 1.f / (1.f + expf(-h));
    g_buf[OFF_H + idx] = rtf32(h);
}

// ---------------------------------------------------------------------------
// per-channel epilogue + kk normalize (R9 version)
// ---------------------------------------------------------------------------
__global__ void __launch_bounds__(256) ew_kernel(
    const float* __restrict__ v_first,
    const float* __restrict__ w0, const float* __restrict__ a0,
    const float* __restrict__ v0p, const float* __restrict__ k_k,
    const float* __restrict__ k_a)
{
    int wid  = blockIdx.x * 8 + (threadIdx.x >> 5);
    int lane = threadIdx.x & 31;
    int t = wid >> 4;
    int h = wid & 15;
    int c0 = h * HS + lane * 2;
    size_t base = (size_t)t * CH + c0;

    float2 tw = *(const float2*)(g_buf + OFF_TW + base);
    float2 ta = *(const float2*)(g_buf + OFF_TA + base);
    float2 tv = *(const float2*)(g_buf + OFF_TV + base);
    float2 kv = *(const float2*)(g_buf + OFF_K + base);
    float2 vv = *(const float2*)(g_buf + OFF_V + base);
    float2 vf = *(const float2*)(v_first + base);
    float2 w0v  = *(const float2*)(w0 + c0);
    float2 a0v  = *(const float2*)(a0 + c0);
    float2 v0v  = *(const float2*)(v0p + c0);
    float2 kkv  = *(const float2*)(k_k + c0);
    float2 kav  = *(const float2*)(k_a + c0);

    auto decay = [](float w0c, float twc) {
        float z = -w0c - twc;
        float sp = (z > 20.f) ? z : log1pf(expf(z));
        float w = -sp - 0.5f;
        return expf(-expf(w));
    };
    float wd0 = decay(w0v.x, tw.x), wd1 = decay(w0v.y, tw.y);

    float aa0 = 1.f / (1.f + expf(-(a0v.x + ta.x)));
    float aa1 = 1.f / (1.f + expf(-(a0v.y + ta.y)));

    float sv0 = 1.f / (1.f + expf(-(v0v.x + tv.x)));
    float sv1 = 1.f / (1.f + expf(-(v0v.y + tv.y)));
    float nv0 = vv.x + (vf.x - vv.x) * sv0;
    float nv1 = vv.y + (vf.y - vv.y) * sv1;

    float kk0 = kv.x * kkv.x, kk1 = kv.y * kkv.y;
    float kn0 = kv.x * (1.f + (aa0 - 1.f) * kav.x);
    float kn1 = kv.y * (1.f + (aa1 - 1.f) * kav.y);

    float ss = kk0 * kk0 + kk1 * kk1;
#pragma unroll
    for (int m = 16; m; m >>= 1) ss += __shfl_xor_sync(0xffffffffu, ss, m);
    float inv = 1.f / fmaxf(sqrtf(ss), 1e-12f);
    float ak0 = kk0 * inv, ak1 = kk1 * inv;
    float bk0 = -ak0 * aa0, bk1 = -ak1 * aa1;

    *(float2*)(g_buf + OFF_WDEC + base) = make_float2(wd0, wd1);
    *(float2*)(g_buf + OFF_V    + base) = make_float2(nv0, nv1);
    *(float2*)(g_buf + OFF_K    + base) = make_float2(kn0, kn1);
    *(float2*)(g_buf + OFF_AKK  + base) = make_float2(ak0, ak1);
    *(float2*)(g_buf + OFF_BKK  + base) = make_float2(bk0, bk1);
}

// ---------------------------------------------------------------------------
// recurrence v2 + f32x2 packed math (bit-identical chain order).
// 128 CTAs (2 per (b,h), 32 rows each), 128 threads = 16 row-pairs x 8 lanes.
// ---------------------------------------------------------------------------
__global__ void __launch_bounds__(128) rec_kernel()
{
    const int bh   = blockIdx.x >> 1;
    const int half = blockIdx.x & 1;
    const int b  = bh >> 4;
    const int h  = bh & 15;
    const int tid = threadIdx.x;
    const int rg  = tid >> 3;
    const int q   = tid & 7;
    const int i0  = half * 32 + rg * 2;
    const int j0  = q * 8;

    __shared__ float sh[2][6][16][64];

    const size_t base = ((size_t)b * 1024) * CH + (size_t)h * HS;
    const float* srcs[6] = {
        g_buf + OFF_R    + base, g_buf + OFF_WDEC + base,
        g_buf + OFF_K    + base, g_buf + OFF_V    + base,
        g_buf + OFF_AKK  + base, g_buf + OFF_BKK  + base };
    float* py = g_buf + OFF_Y + base;

    const uint32_t shaddr = (uint32_t)__cvta_generic_to_shared(&sh[0][0][0][0]);

    auto load_chunk = [&](int bufi, int t0) {
#pragma unroll
        for (int r = 0; r < 12; r++) {
            int idx = tid + 128 * r;
            int arr = idx >> 8;
            int rem = idx & 255;
            int st  = rem >> 4;
            int grp = rem & 15;
            uint32_t dst = shaddr + (uint32_t)(((bufi * 6 + arr) * 16 + st) * 64 + grp * 4) * 4;
            cp16(dst, srcs[arr] + (size_t)(t0 + st) * CH + grp * 4);
        }
        asm volatile("cp.async.commit_group;" ::: "memory");
    };

    float2 s0p[4], s1p[4];
#pragma unroll
    for (int jj = 0; jj < 4; jj++) {
        s0p[jj] = make_float2(0.f, 0.f);
        s1p[jj] = make_float2(0.f, 0.f);
    }

    load_chunk(0, 0);
    asm volatile("cp.async.wait_group 0;" ::: "memory");
    __syncthreads();

    int cur = 0;
    for (int t0 = 0; t0 < 1024; t0 += 16) {
        if (t0 + 16 < 1024) load_chunk(cur ^ 1, t0 + 16);

#pragma unroll 4
        for (int tt = 0; tt < 16; tt++) {
            float4 a4a = *(const float4*)&sh[cur][4][tt][j0];
            float4 a4b = *(const float4*)&sh[cur][4][tt][j0 + 4];
            float2 ap[4] = {{a4a.x, a4a.y}, {a4a.z, a4a.w},
                            {a4b.x, a4b.y}, {a4b.z, a4b.w}};

            // sa: lane.x = even chain, lane.y = odd chain (same order as scalar)
            float2 p0 = f2fma(s0p[0], ap[0], f2fma(s0p[1], ap[1],
                        f2fma(s0p[2], ap[2], f2mul(s0p[3], ap[3]))));
            float2 p1 = f2fma(s1p[0], ap[0], f2fma(s1p[1], ap[1],
                        f2fma(s1p[2], ap[2], f2mul(s1p[3], ap[3]))));
            float sa0 = p0.x + p0.y;
            float sa1 = p1.x + p1.y;
#pragma unroll
            for (int m = 1; m <= 4; m <<= 1) {
                sa0 += __shfl_xor_sync(0xffffffffu, sa0, m);
                sa1 += __shfl_xor_sync(0xffffffffu, sa1, m);
            }

            float2 v2 = *(const float2*)&sh[cur][3][tt][i0];

            float4 w4a = *(const float4*)&sh[cur][1][tt][j0];
            float4 w4b = *(const float4*)&sh[cur][1][tt][j0 + 4];
            float4 k4a = *(const float4*)&sh[cur][2][tt][j0];
            float4 k4b = *(const float4*)&sh[cur][2][tt][j0 + 4];
            float4 b4a = *(const float4*)&sh[cur][5][tt][j0];
            float4 b4b = *(const float4*)&sh[cur][5][tt][j0 + 4];
            float4 r4a = *(const float4*)&sh[cur][0][tt][j0];
            float4 r4b = *(const float4*)&sh[cur][0][tt][j0 + 4];
            float2 wp[4] = {{w4a.x, w4a.y}, {w4a.z, w4a.w}, {w4b.x, w4b.y}, {w4b.z, w4b.w}};
            float2 kp[4] = {{k4a.x, k4a.y}, {k4a.z, k4a.w}, {k4b.x, k4b.y}, {k4b.z, k4b.w}};
            float2 bp[4] = {{b4a.x, b4a.y}, {b4a.z, b4a.w}, {b4b.x, b4b.y}, {b4b.z, b4b.w}};
            float2 rp[4] = {{r4a.x, r4a.y}, {r4a.z, r4a.w}, {r4b.x, r4b.y}, {r4b.z, r4b.w}};

            float2 sab0 = make_float2(sa0, sa0);
            float2 sab1 = make_float2(sa1, sa1);
            float2 vp0  = make_float2(v2.x, v2.x);
            float2 vp1  = make_float2(v2.y, v2.y);

            float2 y0acc = make_float2(0.f, 0.f);
            float2 y1acc = make_float2(0.f, 0.f);
#pragma unroll
            for (int jj = 0; jj < 4; jj++) {
                s0p[jj] = f2fma(sab0, bp[jj], f2fma(vp0, kp[jj], f2mul(s0p[jj], wp[jj])));
                s1p[jj] = f2fma(sab1, bp[jj], f2fma(vp1, kp[jj], f2mul(s1p[jj], wp[jj])));
                y0acc = f2fma(s0p[jj], rp[jj], y0acc);
                y1acc = f2fma(s1p[jj], rp[jj], y1acc);
            }
            float y0 = y0acc.x + y0acc.y;
            float y1 = y1acc.x + y1acc.y;
#pragma unroll
            for (int m = 1; m <= 4; m <<= 1) {
                y0 += __shfl_xor_sync(0xffffffffu, y0, m);
                y1 += __shfl_xor_sync(0xffffffffu, y1, m);
            }
            if (q == 0)
                *(float2*)(py + (size_t)(t0 + tt) * CH + i0) = make_float2(y0, y1);
        }

        asm volatile("cp.async.wait_group 0;" ::: "memory");
        __syncthreads();
        cur ^= 1;
    }
}

// ---------------------------------------------------------------------------
// GroupNorm + bonus + gate (tf32-rounded, k-permuted store: feeds Wo GEMM)
// ---------------------------------------------------------------------------
__global__ void __launch_bounds__(256) post_kernel(
    const float* __restrict__ r_k,
    const float* __restrict__ gn_w, const float* __restrict__ gn_b)
{
    int wid  = blockIdx.x * 8 + (threadIdx.x >> 5);
    int lane = threadIdx.x & 31;
    int t = wid >> 4;
    int h = wid & 15;
    int c0 = h * HS + lane * 2;
    size_t base = (size_t)t * CH + c0;

    float2 yv = *(const float2*)(g_buf + OFF_Y + base);
    float2 rv = *(const float2*)(g_buf + OFF_R + base);
    float2 kv = *(const float2*)(g_buf + OFF_K + base);
    float2 vv = *(const float2*)(g_buf + OFF_V + base);
    float2 gv = *(const float2*)(g_buf + OFF_GATE + base);
    float2 rk = *(const float2*)(r_k + c0);

    float s1 = yv.x + yv.y;
    float s2 = yv.x * yv.x + yv.y * yv.y;
    float s3 = rv.x * kv.x * rk.x + rv.y * kv.y * rk.y;
#pragma unroll
    for (int m = 16; m; m >>= 1) {
        s1 += __shfl_xor_sync(0xffffffffu, s1, m);
        s2 += __shfl_xor_sync(0xffffffffu, s2, m);
        s3 += __shfl_xor_sync(0xffffffffu, s3, m);
    }
    float mu  = s1 * (1.f / 64.f);
    float var = s2 * (1.f / 64.f) - mu * mu;
    float rstd = rsqrtf(var + 0.00064f);

    float2 gw = *(const float2*)(gn_w + c0);
    float2 gb = *(const float2*)(gn_b + c0);
    float o0 = (fmaf((yv.x - mu) * rstd, gw.x, gb.x) + s3 * vv.x) * gv.x;
    float o1 = (fmaf((yv.y - mu) * rstd, gw.y, gb.y) + s3 * vv.y) * gv.y;
    size_t rowb = (size_t)t * CH;
    g_buf[OFF_YP + rowb + pcol(c0)]     = rtf32(o0);
    g_buf[OFF_YP + rowb + pcol(c0 + 1)] = rtf32(o1);
}

// ---------------------------------------------------------------------------
extern "C" void kernel_launch(void* const* d_in, const int* in_sizes, int n_in,
                              void* d_out, int out_size)
{
    (void)in_sizes; (void)n_in; (void)out_size;
    float* buf = nullptr;
    cudaGetSymbolAddress((void**)&buf, g_buf);

    static cudaStream_t s1 = nullptr;
    static cudaEvent_t evFork = nullptr, evPacks = nullptr, evMix = nullptr,
                       evDnW = nullptr, evDnG = nullptr;
    if (s1 == nullptr) {
        cudaStreamCreateWithFlags(&s1, cudaStreamNonBlocking);
        cudaEventCreateWithFlags(&evFork,  cudaEventDisableTiming);
        cudaEventCreateWithFlags(&evPacks, cudaEventDisableTiming);
        cudaEventCreateWithFlags(&evMix,   cudaEventDisableTiming);
        cudaEventCreateWithFlags(&evDnW,   cudaEventDisableTiming);
        cudaEventCreateWithFlags(&evDnG,   cudaEventDisableTiming);
        cudaFuncSetAttribute(gemm_nt_async,  cudaFuncAttributeMaxDynamicSharedMemorySize, SMEM_BYTES);
        cudaFuncSetAttribute(gemm_rkv_async, cudaFuncAttributeMaxDynamicSharedMemorySize, SMEM_BYTES);
        cudaFuncSetAttribute(gemm_dn_async,  cudaFuncAttributeMaxDynamicSharedMemorySize, SMEM_BYTES);
        cudaFuncSetAttribute(gemm_up_async,  cudaFuncAttributeMaxDynamicSharedMemorySize, SMEM_BYTES);
    }

    const float* x    = (const float*)d_in[0];
    const float* vfir = (const float*)d_in[1];
    const float* x_r  = (const float*)d_in[2];
    const float* x_w  = (const float*)d_in[3];
    const float* x_k  = (const float*)d_in[4];
    const float* x_v  = (const float*)d_in[5];
    const float* x_a  = (const float*)d_in[6];
    const float* x_g  = (const float*)d_in[7];
    const float* w0   = (const float*)d_in[8];
    const float* w1   = (const float*)d_in[9];
    const float* w2   = (const float*)d_in[10];
    const float* a0   = (const float*)d_in[11];
    const float* a1   = (const float*)d_in[12];
    const float* a2   = (const float*)d_in[13];
    const float* v0p  = (const float*)d_in[14];
    const float* v1   = (const float*)d_in[15];
    const float* v2   = (const float*)d_in[16];
    const float* g1   = (const float*)d_in[17];
    const float* g2   = (const float*)d_in[18];
    const float* k_k  = (const float*)d_in[19];
    const float* k_a  = (const float*)d_in[20];
    const float* r_k  = (const float*)d_in[21];
    const float* W_r  = (const float*)d_in[22];
    const float* W_k  = (const float*)d_in[23];
    const float* W_v  = (const float*)d_in[24];
    const float* W_o  = (const float*)d_in[25];
    const float* gn_w = (const float*)d_in[26];
    const float* gn_b = (const float*)d_in[27];
    float* out = (float*)d_out;

    // ---- fork side stream ----
    cudaEventRecord(evFork, 0);
    cudaStreamWaitEvent(s1, evFork, 0);

    // s1: weight packs
    pack_rkvo_kernel<<<(4 << 20) / 256, 256, 0, s1>>>(W_r, W_k, W_v, W_o);
    pack_up_kernel<<<(640 * 1024 + 255) / 256, 256, 0, s1>>>(w1, a1, v1, g1);
    pack_dn_kernel<<<(1024 * NUP + 255) / 256, 256, 0, s1>>>(w2, a2, v2, g2);
    cudaEventRecord(evPacks, s1);

    // s0: mixes, then r/k/v
    mix_kernel<<<(int)(SZ / 256), 256>>>(x, x_r, x_w, x_k, x_v, x_a, x_g);
    cudaEventRecord(evMix, 0);
    cudaStreamWaitEvent(0, evPacks, 0);
    gemm_rkv_async<<<dim3(24, TOK / 128), 256, SMEM_BYTES>>>();

    // s1: LoRA chain
    cudaStreamWaitEvent(s1, evMix, 0);
    gemm_up_async<<<dim3(5, TOK / 128, 2), 256, SMEM_BYTES, s1>>>();
    combine_up_kernel<<<TOK * NUP / 256, 256, 0, s1>>>();
    gemm_dn_async<<<dim3(CH / 128, TOK / 128, 3), 256, SMEM_BYTES, s1>>>(0);  // w,a,v
    cudaEventRecord(evDnW, s1);
    gemm_dn_async<<<dim3(CH / 128, TOK / 128, 1), 256, SMEM_BYTES, s1>>>(3);  // gate
    cudaEventRecord(evDnG, s1);

    // s0: join for ew, recurrence
    cudaStreamWaitEvent(0, evDnW, 0);
    ew_kernel<<<TOK * NH / 8, 256>>>(vfir, w0, a0, v0p, k_k, k_a);
    rec_kernel<<<128, 128>>>();

    // s0: join gate, post + Wo
    cudaStreamWaitEvent(0, evDnG, 0);
    post_kernel<<<TOK * NH / 8, 256>>>(r_k, gn_w, gn_b);
    gemm_nt_async<<<dim3(CH / 128, TOK / 128), 256, SMEM_BYTES>>>(
        buf + OFF_YP, CH, buf + OFF_WB + (3u << 20), CH, out, CH, CH);
}

// round 13
// speedup vs baseline: 1.3229x; 1.1416x over previous
#include <cuda_runtime.h>
#include <math.h>
#include <stdint.h>

#define TOK 4096          // B*T
#define CH  1024          // C
#define NH  16            // heads
#define HS  64            // head size
#define NUP 384           // packed LoRA hidden width
#define NSTAGE 5
#define TILEW 2048                       // floats per 128x16 tile (8KB)
#define STG_FLOATS (2 * TILEW)           // A+B tile per stage
#define GSMEM_BYTES (NSTAGE * STG_FLOATS * 4)   // 81920 B

static constexpr size_t SZ = (size_t)TOK * CH;

static constexpr size_t OFF_XR   = 0 * SZ;   // tiled tf32 (rkv A)
static constexpr size_t OFF_XW   = 1 * SZ;   // tiled tf32 (up A)
static constexpr size_t OFF_XK   = 2 * SZ;
static constexpr size_t OFF_XV   = 3 * SZ;
static constexpr size_t OFF_XA   = 4 * SZ;
static constexpr size_t OFF_XG   = 5 * SZ;
static constexpr size_t OFF_R    = 6 * SZ;   // natural fp32 outputs
static constexpr size_t OFF_K    = 7 * SZ;
static constexpr size_t OFF_V    = 8 * SZ;
static constexpr size_t OFF_TW   = 9 * SZ;   // natural fp32 (dn outputs)
static constexpr size_t OFF_TA   = 10 * SZ;
static constexpr size_t OFF_TV   = 11 * SZ;
static constexpr size_t OFF_GATE = 12 * SZ;
static constexpr size_t OFF_WDEC = 13 * SZ;
static constexpr size_t OFF_AKK  = 14 * SZ;
static constexpr size_t OFF_BKK  = 15 * SZ;
static constexpr size_t OFF_Y    = 16 * SZ;
static constexpr size_t OFF_YP   = 17 * SZ;  // tiled tf32 (Wo A)
static constexpr size_t OFF_H    = 18 * SZ;                          // tiled [4096x384]
static constexpr size_t OFF_H1   = 18 * SZ + (size_t)TOK * NUP;
static constexpr size_t OFF_WUPT = 19 * SZ;                          // tiled [640x1024]
static constexpr size_t OFF_WDNT = 19 * SZ + (size_t)640 * 1024;     // tiled [1024x384]
static constexpr size_t OFF_WB   = 20 * SZ;                          // tiled Wr|Wk|Wv|Wo, 1M floats each
static constexpr size_t TOTALF   = 21 * SZ;

__device__ float g_buf[TOTALF];

__device__ __forceinline__ float rtf32(float f) {
    uint32_t u; asm("cvt.rna.tf32.f32 %0, %1;" : "=r"(u) : "f"(f));
    return __uint_as_float(u);
}

// k-permutation within 8-groups (fragment pairs adjacent)
__device__ __forceinline__ int pcol(int k) {
    return (k & ~7) | ((k & 3) << 1) | ((k >> 2) & 1);
}

// tiled layout: 128-row x 16-col tiles, tiles row-major over (rowblk, kchunk);
// within a tile: row*16 + (pcol(col)&15)
__device__ __forceinline__ size_t tiladdr(int row, int col, int ld) {
    int tile = (row >> 7) * (ld >> 4) + (col >> 4);
    int inc  = pcol(col) & 15;
    return (size_t)tile * TILEW + ((row & 127) << 4) + inc;
}

// ---- bulk-copy / mbarrier primitives ----
__device__ __forceinline__ void mb_init(uint32_t mbar, uint32_t cnt) {
    asm volatile("mbarrier.init.shared.b64 [%0], %1;" :: "r"(mbar), "r"(cnt) : "memory");
}
__device__ __forceinline__ void mb_expect(uint32_t mbar, uint32_t bytes) {
    asm volatile("mbarrier.arrive.expect_tx.shared.b64 _, [%0], %1;"
                 :: "r"(mbar), "r"(bytes) : "memory");
}
__device__ __forceinline__ void mb_wait(uint32_t mbar, uint32_t parity) {
    asm volatile("{\n\t.reg .pred P;\n"
                 "W%=:\n\t"
                 "mbarrier.try_wait.parity.acquire.cta.shared::cta.b64 P, [%0], %1;\n\t"
                 "@!P bra W%=;\n\t}"
                 :: "r"(mbar), "r"(parity) : "memory");
}
__device__ __forceinline__ void bulk_ld(uint32_t dst, const float* src, uint32_t mbar) {
    asm volatile("cp.async.bulk.shared::cta.global.mbarrier::complete_tx::bytes [%0], [%1], %2, [%3];"
                 :: "r"(dst), "l"(src), "r"(8192u), "r"(mbar) : "memory");
}

// ---------------------------------------------------------------------------
// 1) token-shift mixes -> tiled tf32
// ---------------------------------------------------------------------------
__global__ void __launch_bounds__(256) mix_kernel(
    const float* __restrict__ x,
    const float* __restrict__ mr, const float* __restrict__ mw,
    const float* __restrict__ mk, const float* __restrict__ mv,
    const float* __restrict__ ma, const float* __restrict__ mg)
{
    int idx = blockIdx.x * 256 + threadIdx.x;
    int c   = idx & (CH - 1);
    int row = idx >> 10;
    int t   = row & 1023;
    float xv = x[idx];
    float lx = (t == 0) ? 0.f : x[idx - CH];
    float dx = lx - xv;
    size_t w = tiladdr(row, c, CH);
    g_buf[OFF_XR + w] = rtf32(fmaf(mr[c], dx, xv));
    g_buf[OFF_XW + w] = rtf32(fmaf(mw[c], dx, xv));
    g_buf[OFF_XK + w] = rtf32(fmaf(mk[c], dx, xv));
    g_buf[OFF_XV + w] = rtf32(fmaf(mv[c], dx, xv));
    g_buf[OFF_XA + w] = rtf32(fmaf(ma[c], dx, xv));
    g_buf[OFF_XG + w] = rtf32(fmaf(mg[c], dx, xv));
}

// ---------------------------------------------------------------------------
// weight packs -> tiled tf32
// ---------------------------------------------------------------------------
__global__ void __launch_bounds__(256) pack_up_kernel(
    const float* __restrict__ w1, const float* __restrict__ a1,
    const float* __restrict__ v1, const float* __restrict__ g1)
{
    int idx = blockIdx.x * 256 + threadIdx.x;   // < 640*1024
    if (idx >= 640 * 1024) return;
    int n = idx >> 10;
    int k = idx & 1023;
    float v = 0.f;
    if      (n < 64)                 v = w1[k * 64  + n];
    else if (n >= 128 && n < 192)    v = a1[k * 64  + (n - 128)];
    else if (n >= 256 && n < 288)    v = v1[k * 32  + (n - 256)];
    else if (n >= 384 && n < 544)    v = g1[k * 160 + (n - 384)];
    g_buf[OFF_WUPT + tiladdr(n, k, 1024)] = rtf32(v);
}

__global__ void __launch_bounds__(256) pack_dn_kernel(
    const float* __restrict__ w2, const float* __restrict__ a2,
    const float* __restrict__ v2, const float* __restrict__ g2)
{
    int idx = blockIdx.x * 256 + threadIdx.x;       // < 1024*384
    if (idx >= 1024 * NUP) return;
    int n  = idx / NUP;
    int kk = idx - n * NUP;
    float v;
    if      (kk < 64)  v = w2[(size_t)kk * 1024 + n];
    else if (kk < 128) v = a2[(size_t)(kk - 64) * 1024 + n];
    else if (kk < 160) v = v2[(size_t)(kk - 128) * 1024 + n];
    else if (kk < 192) v = 0.f;
    else if (kk < 352) v = g2[(size_t)(kk - 192) * 1024 + n];
    else               v = 0.f;
    g_buf[OFF_WDNT + tiladdr(n, kk, NUP)] = rtf32(v);
}

__global__ void __launch_bounds__(256) pack_rkvo_kernel(
    const float* __restrict__ Wr, const float* __restrict__ Wk,
    const float* __restrict__ Wv, const float* __restrict__ Wo)
{
    int idx = blockIdx.x * 256 + threadIdx.x;   // < 4*1M
    int m = idx >> 20;
    int e = idx & ((1 << 20) - 1);
    int n = e >> 10;
    int k = e & 1023;
    const float* src = (m == 0) ? Wr : (m == 1) ? Wk : (m == 2) ? Wv : Wo;
    g_buf[OFF_WB + ((size_t)m << 20) + tiladdr(n, k, 1024)] = rtf32(src[e]);
}

// ---------------------------------------------------------------------------
// tf32 MMA core with cp.async.bulk 5-stage pipeline (NT), tiled inputs.
// A tiles at (m0>>7, (kofsA+k)>>4); B tiles at (n0B>>7, (kofsB+k)>>4).
// permout: scalar stores at tiled positions (outputs feeding GEMM K dims).
// ---------------------------------------------------------------------------
__device__ __forceinline__ void gemm_bulk_core(
    float* sm, uint64_t* mbars,
    const float* At, int lda, int kofsA,
    const float* Bt, int ldb, int kofsB, int n0B,
    float* C, int ldc, int K,
    int m0, int n0C, int col_off, int width, int permout)
{
    const int tid  = threadIdx.x;
    const int lane = tid & 31, warp = tid >> 5;
    const int wm = warp >> 2, wn = warp & 3;
    const int nch = K >> 4;

    const uint32_t smbase = (uint32_t)__cvta_generic_to_shared(sm);
    const uint32_t mbbase = (uint32_t)__cvta_generic_to_shared(mbars);

    const float* Abase = At + ((size_t)(m0  >> 7) * (lda >> 4) + (kofsA >> 4)) * TILEW;
    const float* Bbase = Bt + ((size_t)(n0B >> 7) * (ldb >> 4) + (kofsB >> 4)) * TILEW;

    if (tid == 0)
        for (int s = 0; s < NSTAGE; s++) mb_init(mbbase + 8 * s, 1);
    __syncthreads();
    if (tid == 0) {
        int pre = (nch < NSTAGE) ? nch : NSTAGE;
        for (int s = 0; s < pre; s++) {
            uint32_t mb = mbbase + 8 * s;
            mb_expect(mb, 16384);
            bulk_ld(smbase + (uint32_t)(s * STG_FLOATS) * 4,
                    Abase + (size_t)s * TILEW, mb);
            bulk_ld(smbase + (uint32_t)(s * STG_FLOATS + TILEW) * 4,
                    Bbase + (size_t)s * TILEW, mb);
        }
    }

    float acc[4][4][4];
#pragma unroll
    for (int mt = 0; mt < 4; mt++)
#pragma unroll
        for (int nt = 0; nt < 4; nt++)
#pragma unroll
            for (int r = 0; r < 4; r++) acc[mt][nt][r] = 0.f;

    const int q2 = (lane & 3) * 2;

    int stage = 0;
    for (int i = 0; i < nch; i++) {
        mb_wait(mbbase + 8 * stage, (uint32_t)((i / NSTAGE) & 1));

        const float* As = sm + stage * STG_FLOATS;
        const float* Bs = As + TILEW;
#pragma unroll
        for (int kk = 0; kk < 2; kk++) {
            const int base = kk * 8 + q2;
            uint2 ap0[4], ap1[4], bp[4];
#pragma unroll
            for (int mt = 0; mt < 4; mt++) {
                int r = wm * 64 + mt * 16 + (lane >> 2);
                ap0[mt] = *(const uint2*)&As[r * 16 + base];
                ap1[mt] = *(const uint2*)&As[(r + 8) * 16 + base];
            }
#pragma unroll
            for (int nt = 0; nt < 4; nt++) {
                int n = wn * 32 + nt * 8 + (lane >> 2);
                bp[nt] = *(const uint2*)&Bs[n * 16 + base];
            }
#pragma unroll
            for (int mt = 0; mt < 4; mt++)
#pragma unroll
                for (int nt = 0; nt < 4; nt++) {
                    asm volatile(
                        "mma.sync.aligned.m16n8k8.row.col.f32.tf32.tf32.f32 "
                        "{%0,%1,%2,%3},{%4,%5,%6,%7},{%8,%9},{%0,%1,%2,%3};"
                        : "+f"(acc[mt][nt][0]), "+f"(acc[mt][nt][1]),
                          "+f"(acc[mt][nt][2]), "+f"(acc[mt][nt][3])
                        : "r"(ap0[mt].x), "r"(ap1[mt].x),
                          "r"(ap0[mt].y), "r"(ap1[mt].y),
                          "r"(bp[nt].x), "r"(bp[nt].y));
                }
        }
        __syncthreads();   // all readers done with this stage
        int inx = i + NSTAGE;
        if (inx < nch && tid == 0) {
            uint32_t mb = mbbase + 8 * stage;
            mb_expect(mb, 16384);
            bulk_ld(smbase + (uint32_t)(stage * STG_FLOATS) * 4,
                    Abase + (size_t)inx * TILEW, mb);
            bulk_ld(smbase + (uint32_t)(stage * STG_FLOATS + TILEW) * 4,
                    Bbase + (size_t)inx * TILEW, mb);
        }
        stage = (stage + 1 == NSTAGE) ? 0 : stage + 1;
    }

#pragma unroll
    for (int mt = 0; mt < 4; mt++) {
        int row = m0 + wm * 64 + mt * 16 + (lane >> 2);
#pragma unroll
        for (int nt = 0; nt < 4; nt++) {
            int col = wn * 32 + nt * 8 + (lane & 3) * 2;
            if (col < width) {
                if (permout) {
                    int g0 = col_off + n0C + col;
                    C[tiladdr(row, g0, ldc)]     = acc[mt][nt][0];
                    C[tiladdr(row, g0 + 1, ldc)] = acc[mt][nt][1];
                    C[tiladdr(row + 8, g0, ldc)]     = acc[mt][nt][2];
                    C[tiladdr(row + 8, g0 + 1, ldc)] = acc[mt][nt][3];
                } else {
                    int gcol = col_off + n0C + col;
                    *(float2*)(C + (size_t)row * ldc + gcol) =
                        make_float2(acc[mt][nt][0], acc[mt][nt][1]);
                    *(float2*)(C + (size_t)(row + 8) * ldc + gcol) =
                        make_float2(acc[mt][nt][2], acc[mt][nt][3]);
                }
            }
        }
    }
}

__global__ void __launch_bounds__(256) gemm_nt_bulk(
    const float* __restrict__ A, int lda,
    const float* __restrict__ B, int ldb,
    float* __restrict__ C, int ldc, int K)
{
    extern __shared__ float sm[];
    __shared__ uint64_t mbars[NSTAGE];
    gemm_bulk_core(sm, mbars, A, lda, 0, B, ldb, 0, blockIdx.x * 128,
                   C, ldc, K, blockIdx.y * 128, blockIdx.x * 128, 0, 1 << 30, 0);
}

__global__ void __launch_bounds__(256) gemm_rkv_bulk()
{
    extern __shared__ float sm[];
    __shared__ uint64_t mbars[NSTAGE];
    const int p  = blockIdx.x >> 3;
    const int n0 = (blockIdx.x & 7) * 128;
    const float* A = g_buf + ((p == 0) ? OFF_XR : (p == 1) ? OFF_XK : OFF_XV);
    const float* B = g_buf + OFF_WB + ((size_t)p << 20);
    float* C = g_buf + OFF_R + (size_t)p * SZ;
    gemm_bulk_core(sm, mbars, A, CH, 0, B, CH, 0, n0,
                   C, CH, CH, blockIdx.y * 128, n0, 0, 1 << 30, 0);
}

__global__ void __launch_bounds__(256) gemm_dn_bulk(int zbase)
{
    extern __shared__ float sm[];
    __shared__ uint64_t mbars[NSTAGE];
    const int z = zbase + blockIdx.z;
    const int koff = (z == 0) ? 0 : (z == 1) ? 64 : (z == 2) ? 128 : 192;
    const int Kz   = (z == 0) ? 64 : (z == 1) ? 64 : (z == 2) ? 32 : 160;
    float* C = g_buf + OFF_TW + (size_t)z * SZ;
    gemm_bulk_core(sm, mbars, g_buf + OFF_H, NUP, koff,
                   g_buf + OFF_WDNT, NUP, koff, blockIdx.x * 128,
                   C, CH, Kz, blockIdx.y * 128, blockIdx.x * 128, 0, 1 << 30, 0);
}

// LoRA up-projection, split-K2, tiled-permuted epilogue
__global__ void __launch_bounds__(256) gemm_up_bulk()
{
    extern __shared__ float sm[];
    __shared__ uint64_t mbars[NSTAGE];
    const int tile = blockIdx.x;
    const int kz   = blockIdx.z;
    const int seg  = (tile <= 3) ? tile : 3;
    const int brow = seg * 128 + ((tile == 4) ? 128 : 0);
    const int coff = (tile == 0) ? 0 : (tile == 1) ? 64 : (tile == 2) ? 128 :
                     (tile == 3) ? 192 : 320;
    const int wid  = (tile == 0) ? 64 : (tile == 1) ? 64 : (tile == 2) ? 32 :
                     (tile == 3) ? 128 : 32;
    const size_t aoff = (seg == 0) ? OFF_XW : (seg == 1) ? OFF_XA :
                        (seg == 2) ? OFF_XV : OFF_XG;
    float* C = g_buf + (kz ? OFF_H1 : OFF_H);
    gemm_bulk_core(sm, mbars, g_buf + aoff, CH, kz * 512,
                   g_buf + OFF_WUPT, 1024, kz * 512, brow,
                   C, NUP, 512, blockIdx.y * 128, 0, coff, wid, 1);
}

// combine split-K halves + activations (tiled layout; region by k-chunk)
__global__ void __launch_bounds__(256) combine_up_kernel()
{
    int idx = blockIdx.x * 256 + threadIdx.x;    // < TOK*NUP
    float h = g_buf[OFF_H + idx] + g_buf[OFF_H1 + idx];
    int kc = (idx >> 11) % 24;                   // k-chunk of this tile
    if (kc < 4)                   h = tanhf(h);
    else if (kc >= 12 && kc < 22) h = 1.f / (1.f + expf(-h));
    g_buf[OFF_H + idx] = rtf32(h);
}

// ---------------------------------------------------------------------------
// per-channel epilogue + kk normalize (natural layouts)
// ---------------------------------------------------------------------------
__global__ void __launch_bounds__(256) ew_kernel(
    const float* __restrict__ v_first,
    const float* __restrict__ w0, const float* __restrict__ a0,
    const float* __restrict__ v0p, const float* __restrict__ k_k,
    const float* __restrict__ k_a)
{
    int wid  = blockIdx.x * 8 + (threadIdx.x >> 5);
    int lane = threadIdx.x & 31;
    int t = wid >> 4;
    int h = wid & 15;
    int c0 = h * HS + lane * 2;
    size_t base = (size_t)t * CH + c0;

    float2 tw = *(const float2*)(g_buf + OFF_TW + base);
    float2 ta = *(const float2*)(g_buf + OFF_TA + base);
    float2 tv = *(const float2*)(g_buf + OFF_TV + base);
    float2 kv = *(const float2*)(g_buf + OFF_K + base);
    float2 vv = *(const float2*)(g_buf + OFF_V + base);
    float2 vf = *(const float2*)(v_first + base);
    float2 w0v  = *(const float2*)(w0 + c0);
    float2 a0v  = *(const float2*)(a0 + c0);
    float2 v0v  = *(const float2*)(v0p + c0);
    float2 kkv  = *(const float2*)(k_k + c0);
    float2 kav  = *(const float2*)(k_a + c0);

    auto decay = [](float w0c, float twc) {
        float z = -w0c - twc;
        float sp = (z > 20.f) ? z : log1pf(expf(z));
        float w = -sp - 0.5f;
        return expf(-expf(w));
    };
    float wd0 = decay(w0v.x, tw.x), wd1 = decay(w0v.y, tw.y);

    float aa0 = 1.f / (1.f + expf(-(a0v.x + ta.x)));
    float aa1 = 1.f / (1.f + expf(-(a0v.y + ta.y)));

    float sv0 = 1.f / (1.f + expf(-(v0v.x + tv.x)));
    float sv1 = 1.f / (1.f + expf(-(v0v.y + tv.y)));
    float nv0 = vv.x + (vf.x - vv.x) * sv0;
    float nv1 = vv.y + (vf.y - vv.y) * sv1;

    float kk0 = kv.x * kkv.x, kk1 = kv.y * kkv.y;
    float kn0 = kv.x * (1.f + (aa0 - 1.f) * kav.x);
    float kn1 = kv.y * (1.f + (aa1 - 1.f) * kav.y);

    float ss = kk0 * kk0 + kk1 * kk1;
#pragma unroll
    for (int m = 16; m; m >>= 1) ss += __shfl_xor_sync(0xffffffffu, ss, m);
    float inv = 1.f / fmaxf(sqrtf(ss), 1e-12f);
    float ak0 = kk0 * inv, ak1 = kk1 * inv;
    float bk0 = -ak0 * aa0, bk1 = -ak1 * aa1;

    *(float2*)(g_buf + OFF_WDEC + base) = make_float2(wd0, wd1);
    *(float2*)(g_buf + OFF_V    + base) = make_float2(nv0, nv1);
    *(float2*)(g_buf + OFF_K    + base) = make_float2(kn0, kn1);
    *(float2*)(g_buf + OFF_AKK  + base) = make_float2(ak0, ak1);
    *(float2*)(g_buf + OFF_BKK  + base) = make_float2(bk0, bk1);
}

// ---------------------------------------------------------------------------
// recurrence (R12 f32x2 version, unchanged)
// ---------------------------------------------------------------------------
__device__ __forceinline__ float2 f2mul(float2 a, float2 b) {
    unsigned long long ra = *(unsigned long long*)&a;
    unsigned long long rb = *(unsigned long long*)&b;
    unsigned long long rd;
    asm("mul.rn.f32x2 %0, %1, %2;" : "=l"(rd) : "l"(ra), "l"(rb));
    return *(float2*)&rd;
}
__device__ __forceinline__ float2 f2fma(float2 a, float2 b, float2 c) {
    unsigned long long ra = *(unsigned long long*)&a;
    unsigned long long rb = *(unsigned long long*)&b;
    unsigned long long rc = *(unsigned long long*)&c;
    unsigned long long rd;
    asm("fma.rn.f32x2 %0, %1, %2, %3;" : "=l"(rd) : "l"(ra), "l"(rb), "l"(rc));
    return *(float2*)&rd;
}

__device__ __forceinline__ void cp16(uint32_t dst, const float* src) {
    asm volatile("cp.async.cg.shared.global [%0], [%1], 16;" :: "r"(dst), "l"(src));
}

__global__ void __launch_bounds__(128) rec_kernel()
{
    const int bh   = blockIdx.x >> 1;
    const int half = blockIdx.x & 1;
    const int b  = bh >> 4;
    const int h  = bh & 15;
    const int tid = threadIdx.x;
    const int rg  = tid >> 3;
    const int q   = tid & 7;
    const int i0  = half * 32 + rg * 2;
    const int j0  = q * 8;

    __shared__ float sh[2][6][16][64];

    const size_t base = ((size_t)b * 1024) * CH + (size_t)h * HS;
    const float* srcs[6] = {
        g_buf + OFF_R    + base, g_buf + OFF_WDEC + base,
        g_buf + OFF_K    + base, g_buf + OFF_V    + base,
        g_buf + OFF_AKK  + base, g_buf + OFF_BKK  + base };
    float* py = g_buf + OFF_Y + base;

    const uint32_t shaddr = (uint32_t)__cvta_generic_to_shared(&sh[0][0][0][0]);

    auto load_chunk = [&](int bufi, int t0) {
#pragma unroll
        for (int r = 0; r < 12; r++) {
            int idx = tid + 128 * r;
            int arr = idx >> 8;
            int rem = idx & 255;
            int st  = rem >> 4;
            int grp = rem & 15;
            uint32_t dst = shaddr + (uint32_t)(((bufi * 6 + arr) * 16 + st) * 64 + grp * 4) * 4;
            cp16(dst, srcs[arr] + (size_t)(t0 + st) * CH + grp * 4);
        }
        asm volatile("cp.async.commit_group;" ::: "memory");
    };

    float2 s0p[4], s1p[4];
#pragma unroll
    for (int jj = 0; jj < 4; jj++) {
        s0p[jj] = make_float2(0.f, 0.f);
        s1p[jj] = make_float2(0.f, 0.f);
    }

    load_chunk(0, 0);
    asm volatile("cp.async.wait_group 0;" ::: "memory");
    __syncthreads();

    int cur = 0;
    for (int t0 = 0; t0 < 1024; t0 += 16) {
        if (t0 + 16 < 1024) load_chunk(cur ^ 1, t0 + 16);

#pragma unroll 4
        for (int tt = 0; tt < 16; tt++) {
            float4 a4a = *(const float4*)&sh[cur][4][tt][j0];
            float4 a4b = *(const float4*)&sh[cur][4][tt][j0 + 4];
            float2 ap[4] = {{a4a.x, a4a.y}, {a4a.z, a4a.w},
                            {a4b.x, a4b.y}, {a4b.z, a4b.w}};

            float2 p0 = f2fma(s0p[0], ap[0], f2fma(s0p[1], ap[1],
                        f2fma(s0p[2], ap[2], f2mul(s0p[3], ap[3]))));
            float2 p1 = f2fma(s1p[0], ap[0], f2fma(s1p[1], ap[1],
                        f2fma(s1p[2], ap[2], f2mul(s1p[3], ap[3]))));
            float sa0 = p0.x + p0.y;
            float sa1 = p1.x + p1.y;
#pragma unroll
            for (int m = 1; m <= 4; m <<= 1) {
                sa0 += __shfl_xor_sync(0xffffffffu, sa0, m);
                sa1 += __shfl_xor_sync(0xffffffffu, sa1, m);
            }

            float2 v2 = *(const float2*)&sh[cur][3][tt][i0];

            float4 w4a = *(const float4*)&sh[cur][1][tt][j0];
            float4 w4b = *(const float4*)&sh[cur][1][tt][j0 + 4];
            float4 k4a = *(const float4*)&sh[cur][2][tt][j0];
            float4 k4b = *(const float4*)&sh[cur][2][tt][j0 + 4];
            float4 b4a = *(const float4*)&sh[cur][5][tt][j0];
            float4 b4b = *(const float4*)&sh[cur][5][tt][j0 + 4];
            float4 r4a = *(const float4*)&sh[cur][0][tt][j0];
            float4 r4b = *(const float4*)&sh[cur][0][tt][j0 + 4];
            float2 wp[4] = {{w4a.x, w4a.y}, {w4a.z, w4a.w}, {w4b.x, w4b.y}, {w4b.z, w4b.w}};
            float2 kp[4] = {{k4a.x, k4a.y}, {k4a.z, k4a.w}, {k4b.x, k4b.y}, {k4b.z, k4b.w}};
            float2 bp[4] = {{b4a.x, b4a.y}, {b4a.z, b4a.w}, {b4b.x, b4b.y}, {b4b.z, b4b.w}};
            float2 rp[4] = {{r4a.x, r4a.y}, {r4a.z, r4a.w}, {r4b.x, r4b.y}, {r4b.z, r4b.w}};

            float2 sab0 = make_float2(sa0, sa0);
            float2 sab1 = make_float2(sa1, sa1);
            float2 vp0  = make_float2(v2.x, v2.x);
            float2 vp1  = make_float2(v2.y, v2.y);

            float2 y0acc = make_float2(0.f, 0.f);
            float2 y1acc = make_float2(0.f, 0.f);
#pragma unroll
            for (int jj = 0; jj < 4; jj++) {
                s0p[jj] = f2fma(sab0, bp[jj], f2fma(vp0, kp[jj], f2mul(s0p[jj], wp[jj])));
                s1p[jj] = f2fma(sab1, bp[jj], f2fma(vp1, kp[jj], f2mul(s1p[jj], wp[jj])));
                y0acc = f2fma(s0p[jj], rp[jj], y0acc);
                y1acc = f2fma(s1p[jj], rp[jj], y1acc);
            }
            float y0 = y0acc.x + y0acc.y;
            float y1 = y1acc.x + y1acc.y;
#pragma unroll
            for (int m = 1; m <= 4; m <<= 1) {
                y0 += __shfl_xor_sync(0xffffffffu, y0, m);
                y1 += __shfl_xor_sync(0xffffffffu, y1, m);
            }
            if (q == 0)
                *(float2*)(py + (size_t)(t0 + tt) * CH + i0) = make_float2(y0, y1);
        }

        asm volatile("cp.async.wait_group 0;" ::: "memory");
        __syncthreads();
        cur ^= 1;
    }
}

// ---------------------------------------------------------------------------
// GroupNorm + bonus + gate (tiled tf32 store: feeds Wo GEMM)
// ---------------------------------------------------------------------------
__global__ void __launch_bounds__(256) post_kernel(
    const float* __restrict__ r_k,
    const float* __restrict__ gn_w, const float* __restrict__ gn_b)
{
    int wid  = blockIdx.x * 8 + (threadIdx.x >> 5);
    int lane = threadIdx.x & 31;
    int t = wid >> 4;
    int h = wid & 15;
    int c0 = h * HS + lane * 2;
    size_t base = (size_t)t * CH + c0;

    float2 yv = *(const float2*)(g_buf + OFF_Y + base);
    float2 rv = *(const float2*)(g_buf + OFF_R + base);
    float2 kv = *(const float2*)(g_buf + OFF_K + base);
    float2 vv = *(const float2*)(g_buf + OFF_V + base);
    float2 gv = *(const float2*)(g_buf + OFF_GATE + base);
    float2 rk = *(const float2*)(r_k + c0);

    float s1 = yv.x + yv.y;
    float s2 = yv.x * yv.x + yv.y * yv.y;
    float s3 = rv.x * kv.x * rk.x + rv.y * kv.y * rk.y;
#pragma unroll
    for (int m = 16; m; m >>= 1) {
        s1 += __shfl_xor_sync(0xffffffffu, s1, m);
        s2 += __shfl_xor_sync(0xffffffffu, s2, m);
        s3 += __shfl_xor_sync(0xffffffffu, s3, m);
    }
    float mu  = s1 * (1.f / 64.f);
    float var = s2 * (1.f / 64.f) - mu * mu;
    float rstd = rsqrtf(var + 0.00064f);

    float2 gw = *(const float2*)(gn_w + c0);
    float2 gb = *(const float2*)(gn_b + c0);
    float o0 = (fmaf((yv.x - mu) * rstd, gw.x, gb.x) + s3 * vv.x) * gv.x;
    float o1 = (fmaf((yv.y - mu) * rstd, gw.y, gb.y) + s3 * vv.y) * gv.y;
    g_buf[OFF_YP + tiladdr(t, c0, CH)]     = rtf32(o0);
    g_buf[OFF_YP + tiladdr(t, c0 + 1, CH)] = rtf32(o1);
}

// ---------------------------------------------------------------------------
extern "C" void kernel_launch(void* const* d_in, const int* in_sizes, int n_in,
                              void* d_out, int out_size)
{
    (void)in_sizes; (void)n_in; (void)out_size;
    float* buf = nullptr;
    cudaGetSymbolAddress((void**)&buf, g_buf);

    static cudaStream_t s1 = nullptr;
    static cudaEvent_t evFork = nullptr, evPacks = nullptr, evMix = nullptr,
                       evDnW = nullptr, evDnG = nullptr;
    if (s1 == nullptr) {
        cudaStreamCreateWithFlags(&s1, cudaStreamNonBlocking);
        cudaEventCreateWithFlags(&evFork,  cudaEventDisableTiming);
        cudaEventCreateWithFlags(&evPacks, cudaEventDisableTiming);
        cudaEventCreateWithFlags(&evMix,   cudaEventDisableTiming);
        cudaEventCreateWithFlags(&evDnW,   cudaEventDisableTiming);
        cudaEventCreateWithFlags(&evDnG,   cudaEventDisableTiming);
        cudaFuncSetAttribute(gemm_nt_bulk,  cudaFuncAttributeMaxDynamicSharedMemorySize, GSMEM_BYTES);
        cudaFuncSetAttribute(gemm_rkv_bulk, cudaFuncAttributeMaxDynamicSharedMemorySize, GSMEM_BYTES);
        cudaFuncSetAttribute(gemm_dn_bulk,  cudaFuncAttributeMaxDynamicSharedMemorySize, GSMEM_BYTES);
        cudaFuncSetAttribute(gemm_up_bulk,  cudaFuncAttributeMaxDynamicSharedMemorySize, GSMEM_BYTES);
    }

    const float* x    = (const float*)d_in[0];
    const float* vfir = (const float*)d_in[1];
    const float* x_r  = (const float*)d_in[2];
    const float* x_w  = (const float*)d_in[3];
    const float* x_k  = (const float*)d_in[4];
    const float* x_v  = (const float*)d_in[5];
    const float* x_a  = (const float*)d_in[6];
    const float* x_g  = (const float*)d_in[7];
    const float* w0   = (const float*)d_in[8];
    const float* w1   = (const float*)d_in[9];
    const float* w2   = (const float*)d_in[10];
    const float* a0   = (const float*)d_in[11];
    const float* a1   = (const float*)d_in[12];
    const float* a2   = (const float*)d_in[13];
    const float* v0p  = (const float*)d_in[14];
    const float* v1   = (const float*)d_in[15];
    const float* v2   = (const float*)d_in[16];
    const float* g1   = (const float*)d_in[17];
    const float* g2   = (const float*)d_in[18];
    const float* k_k  = (const float*)d_in[19];
    const float* k_a  = (const float*)d_in[20];
    const float* r_k  = (const float*)d_in[21];
    const float* W_r  = (const float*)d_in[22];
    const float* W_k  = (const float*)d_in[23];
    const float* W_v  = (const float*)d_in[24];
    const float* W_o  = (const float*)d_in[25];
    const float* gn_w = (const float*)d_in[26];
    const float* gn_b = (const float*)d_in[27];
    float* out = (float*)d_out;

    // ---- fork side stream ----
    cudaEventRecord(evFork, 0);
    cudaStreamWaitEvent(s1, evFork, 0);

    // s1: weight packs (tiled)
    pack_rkvo_kernel<<<(4 << 20) / 256, 256, 0, s1>>>(W_r, W_k, W_v, W_o);
    pack_up_kernel<<<(640 * 1024 + 255) / 256, 256, 0, s1>>>(w1, a1, v1, g1);
    pack_dn_kernel<<<(1024 * NUP + 255) / 256, 256, 0, s1>>>(w2, a2, v2, g2);
    cudaEventRecord(evPacks, s1);

    // s0: mixes (tiled), then r/k/v
    mix_kernel<<<(int)(SZ / 256), 256>>>(x, x_r, x_w, x_k, x_v, x_a, x_g);
    cudaEventRecord(evMix, 0);
    cudaStreamWaitEvent(0, evPacks, 0);
    gemm_rkv_bulk<<<dim3(24, TOK / 128), 256, GSMEM_BYTES>>>();

    // s1: LoRA chain
    cudaStreamWaitEvent(s1, evMix, 0);
    gemm_up_bulk<<<dim3(5, TOK / 128, 2), 256, GSMEM_BYTES, s1>>>();
    combine_up_kernel<<<TOK * NUP / 256, 256, 0, s1>>>();
    gemm_dn_bulk<<<dim3(CH / 128, TOK / 128, 3), 256, GSMEM_BYTES, s1>>>(0);  // w,a,v
    cudaEventRecord(evDnW, s1);
    gemm_dn_bulk<<<dim3(CH / 128, TOK / 128, 1), 256, GSMEM_BYTES, s1>>>(3);  // gate
    cudaEventRecord(evDnG, s1);

    // s0: join for ew, recurrence
    cudaStreamWaitEvent(0, evDnW, 0);
    ew_kernel<<<TOK * NH / 8, 256>>>(vfir, w0, a0, v0p, k_k, k_a);
    rec_kernel<<<128, 128>>>();

    // s0: join gate, post + Wo
    cudaStreamWaitEvent(0, evDnG, 0);
    post_kernel<<<TOK * NH / 8, 256>>>(r_k, gn_w, gn_b);
    gemm_nt_bulk<<<dim3(CH / 128, TOK / 128), 256, GSMEM_BYTES>>>(
        buf + OFF_YP, CH, buf + OFF_WB + (3u << 20), CH, out, CH, CH);
}